// round 9
// baseline (speedup 1.0000x reference)
#include <cuda_runtime.h>
#include <cuda_bf16.h>
#include <stdint.h>
#include <math.h>

#define SEQ 2048
#define HDIM 1024
#define NLAYER 4
#define NH 16
#define NKV 4
#define HD 64
#define IDIM 4096
#define VOCAB 32000
#define QKVN 1536
#define GUN 8192

// ---------------- scratch ----------------
__device__ float g_h[SEQ * HDIM];
__device__ float g_norm[SEQ * HDIM];
__device__ float g_qkv[SEQ * QKVN];
__device__ float g_att[SEQ * NH * HD];
__device__ float g_gu[SEQ * GUN];
__device__ float g_act[SEQ * IDIM];

__device__ uint32_t wp_qkv[NLAYER * HDIM * QKVN];
__device__ uint32_t wp_o[NLAYER * HDIM * HDIM];
__device__ uint32_t wp_gu[NLAYER * HDIM * GUN];
__device__ uint32_t wp_down[NLAYER * IDIM * HDIM];
__device__ uint32_t wp_lm[HDIM * VOCAB];

// ---------------- helpers ----------------
__device__ __forceinline__ uint32_t pack_bf16(float a, float b) {
    __nv_bfloat162 t = __floats2bfloat162_rn(a, b);
    return *(uint32_t*)&t;
}

__device__ __forceinline__ void split2(float x, float y, uint32_t& hi, uint32_t& lo) {
    __nv_bfloat162 h = __floats2bfloat162_rn(x, y);
    hi = *(uint32_t*)&h;
    __nv_bfloat162 l = __floats2bfloat162_rn(x - __bfloat162float(h.x),
                                             y - __bfloat162float(h.y));
    lo = *(uint32_t*)&l;
}

__device__ __forceinline__ void mma_bf16(float* c, const uint32_t* a, const uint32_t* b) {
    asm volatile(
        "mma.sync.aligned.m16n8k16.row.col.f32.bf16.bf16.f32 "
        "{%0,%1,%2,%3}, {%4,%5,%6,%7}, {%8,%9}, {%0,%1,%2,%3};"
        : "+f"(c[0]), "+f"(c[1]), "+f"(c[2]), "+f"(c[3])
        : "r"(a[0]), "r"(a[1]), "r"(a[2]), "r"(a[3]), "r"(b[0]), "r"(b[1]));
}

__device__ __forceinline__ void cp_async16(void* smem, const void* gmem) {
    uint32_t s = (uint32_t)__cvta_generic_to_shared(smem);
    asm volatile("cp.async.cg.shared.global [%0], [%1], 16;" :: "r"(s), "l"(gmem));
}
#define CP_COMMIT() asm volatile("cp.async.commit_group;")
#define CP_WAIT0()  asm volatile("cp.async.wait_group 0;")

// ---------------- weight prep ----------------
__global__ void prep_w_kernel(const float* __restrict__ s0, int st0,
                              const float* __restrict__ s1, int st1,
                              const float* __restrict__ s2, int st2,
                              int n1, int n2, uint32_t* __restrict__ out) {
    int kt = blockIdx.y, nt = blockIdx.x, NT = gridDim.x;
    int t = threadIdx.x;
#pragma unroll
    for (int it = 0; it < 4; it++) {
        int slot = it * 256 + t;
        int lane = slot & 31, in = (slot >> 5) & 15, ik = slot >> 9;
        int g = lane >> 2, c = lane & 3;
        int n = nt * 128 + in * 8 + g;
        int kb = kt * 32 + ik * 16 + 2 * c;
        const float* src; int nn; int st;
        if (n >= n2)      { src = s2; nn = n - n2; st = st2; }
        else if (n >= n1) { src = s1; nn = n - n1; st = st1; }
        else              { src = s0; nn = n;      st = st0; }
        float x0 = src[(size_t)(kb + 0) * st + nn];
        float x1 = src[(size_t)(kb + 1) * st + nn];
        float x8 = src[(size_t)(kb + 8) * st + nn];
        float x9 = src[(size_t)(kb + 9) * st + nn];
        uint4 o;
        uint32_t l01, l89;
        split2(x0, x1, o.x, l01);
        split2(x8, x9, o.y, l89);
        o.z = l01; o.w = l89;
        *(uint4*)&out[((size_t)((size_t)kt * NT + nt) * 1024 + slot) * 4] = o;
    }
}

// ---------------- bf16x2 (3-term) tensor-core GEMM ----------------
__global__ __launch_bounds__(256) void gemm_bf16x2_kernel(
    const float* __restrict__ A, const uint32_t* __restrict__ Bp,
    const float* __restrict__ Res, float* __restrict__ C,
    int M, int N, int K) {
    __shared__ uint32_t Asm[2][4096];
    __shared__ uint32_t Bsm[2][4096];

    int tid = threadIdx.x, lane = tid & 31, warp = tid >> 5;
    int wm = warp >> 2, wn = warp & 3;
    int bm = blockIdx.y * 128, bnx = blockIdx.x;
    int NT = N >> 7, KT = K >> 5;

    float acc[4][4][4];
#pragma unroll
    for (int im = 0; im < 4; im++)
#pragma unroll
        for (int in = 0; in < 4; in++)
#pragma unroll
            for (int r = 0; r < 4; r++) acc[im][in][r] = 0.f;

    float4 pa[4];

#define LDGA(kt)                                                                     \
    {                                                                                \
        _Pragma("unroll")                                                            \
        for (int i = 0; i < 4; i++) {                                                \
            int f = tid + i * 256;                                                   \
            pa[i] = *(const float4*)(A + (size_t)(bm + (f >> 3)) * K + (kt) * 32 + ((f & 7) << 2)); \
        }                                                                            \
    }

#define CPB(kt, st)                                                                  \
    {                                                                                \
        _Pragma("unroll")                                                            \
        for (int i = 0; i < 4; i++) {                                                \
            int slot = tid + i * 256;                                                \
            cp_async16(&Bsm[st][slot * 4],                                           \
                       Bp + ((size_t)((size_t)(kt) * NT + bnx) * 1024 + slot) * 4);  \
        }                                                                            \
    }

#define STSA(st)                                                                     \
    {                                                                                \
        _Pragma("unroll")                                                            \
        for (int i = 0; i < 4; i++) {                                                \
            int f = tid + i * 256;                                                   \
            int row = f >> 3, k0 = (f & 7) << 2;                                     \
            int ik = k0 >> 4, h = (k0 >> 3) & 1, c0 = (k0 & 7) >> 1;                 \
            int im = row >> 4, reg = ((row >> 3) & 1) + (h << 1);                    \
            int lane0 = ((row & 7) << 2) + c0;                                       \
            float4 v = pa[i];                                                        \
            uint32_t h01, l01, h23, l23;                                             \
            split2(v.x, v.y, h01, l01);                                              \
            split2(v.z, v.w, h23, l23);                                              \
            int baseHi = ((ik * 8 + im) * 2 + 0) * 32;                               \
            int baseLo = ((ik * 8 + im) * 2 + 1) * 32;                               \
            Asm[st][(baseHi + lane0) * 4 + reg]     = h01;                           \
            Asm[st][(baseHi + lane0 + 1) * 4 + reg] = h23;                           \
            Asm[st][(baseLo + lane0) * 4 + reg]     = l01;                           \
            Asm[st][(baseLo + lane0 + 1) * 4 + reg] = l23;                           \
        }                                                                            \
    }

#define COMPUTE(st)                                                                  \
    {                                                                                \
        _Pragma("unroll")                                                            \
        for (int ik = 0; ik < 2; ik++) {                                             \
            uint32_t ah[4][4], al[4][4], bh[4][2], bl[4][2];                         \
            _Pragma("unroll")                                                        \
            for (int im = 0; im < 4; im++) {                                         \
                *(uint4*)ah[im] = *(const uint4*)&Asm[st][(((ik * 8 + wm * 4 + im) * 2 + 0) * 32 + lane) * 4]; \
                *(uint4*)al[im] = *(const uint4*)&Asm[st][(((ik * 8 + wm * 4 + im) * 2 + 1) * 32 + lane) * 4]; \
            }                                                                        \
            _Pragma("unroll")                                                        \
            for (int in = 0; in < 4; in++) {                                         \
                uint4 qv = *(const uint4*)&Bsm[st][((ik * 16 + wn * 4 + in) * 32 + lane) * 4]; \
                bh[in][0] = qv.x; bh[in][1] = qv.y;                                  \
                bl[in][0] = qv.z; bl[in][1] = qv.w;                                  \
            }                                                                        \
            _Pragma("unroll")                                                        \
            for (int im = 0; im < 4; im++)                                           \
                _Pragma("unroll")                                                    \
                for (int in = 0; in < 4; in++) {                                     \
                    mma_bf16(acc[im][in], ah[im], bl[in]);                           \
                    mma_bf16(acc[im][in], al[im], bh[in]);                           \
                    mma_bf16(acc[im][in], ah[im], bh[in]);                           \
                }                                                                    \
        }                                                                            \
    }

    LDGA(0);
    CPB(0, 0); CP_COMMIT();
    STSA(0);
    CP_WAIT0();
    __syncthreads();

    for (int kt = 0; kt < KT; kt++) {
        int st = kt & 1;
        if (kt + 1 < KT) { LDGA(kt + 1); CPB(kt + 1, st ^ 1); CP_COMMIT(); }
        COMPUTE(st);
        if (kt + 1 < KT) { STSA(st ^ 1); CP_WAIT0(); }
        __syncthreads();
    }

    int gid = lane >> 2, tig = lane & 3;
#pragma unroll
    for (int im = 0; im < 4; im++) {
#pragma unroll
        for (int in = 0; in < 4; in++) {
            int row0 = bm + wm * 64 + im * 16 + gid;
            int col = bnx * 128 + wn * 32 + in * 8 + tig * 2;
            float2 v0 = make_float2(acc[im][in][0], acc[im][in][1]);
            float2 v1 = make_float2(acc[im][in][2], acc[im][in][3]);
            if (Res) {
                float2 r0 = *(const float2*)(Res + (size_t)row0 * N + col);
                float2 r1 = *(const float2*)(Res + (size_t)(row0 + 8) * N + col);
                v0.x += r0.x; v0.y += r0.y;
                v1.x += r1.x; v1.y += r1.y;
            }
            *(float2*)(C + (size_t)row0 * N + col) = v0;
            *(float2*)(C + (size_t)(row0 + 8) * N + col) = v1;
        }
    }
#undef LDGA
#undef CPB
#undef STSA
#undef COMPUTE
}

// ---------------- embedding + audio scatter ----------------
__global__ void embed_scatter_kernel(const int* __restrict__ ids,
                                     const float* __restrict__ emb,
                                     const float* __restrict__ audio,
                                     const int* __restrict__ aoff,
                                     float* __restrict__ h) {
    int s = blockIdx.x;
    int off = aoff[0];
    const float* src;
    if (s >= off && s < off + 256) src = audio + (size_t)(s - off) * HDIM;
    else                           src = emb + (size_t)ids[s] * HDIM;
    float* dst = h + (size_t)s * HDIM;
    int i = threadIdx.x * 4;
    *(float4*)&dst[i] = *(const float4*)&src[i];
}

// ---------------- RMSNorm H=1024 ----------------
__global__ void rmsnorm_kernel(const float* __restrict__ x,
                               const float* __restrict__ w,
                               float* __restrict__ out) {
    int s = blockIdx.x;
    const float* xr = x + (size_t)s * HDIM;
    float ss = 0.f;
#pragma unroll
    for (int i = 0; i < 4; i++) { float v = xr[threadIdx.x + i * 256]; ss += v * v; }
    __shared__ float red[8];
#pragma unroll
    for (int o = 16; o; o >>= 1) ss += __shfl_xor_sync(0xffffffffu, ss, o);
    if ((threadIdx.x & 31) == 0) red[threadIdx.x >> 5] = ss;
    __syncthreads();
    if (threadIdx.x < 32) {
        float v = (threadIdx.x < 8) ? red[threadIdx.x] : 0.f;
#pragma unroll
        for (int o = 4; o; o >>= 1) v += __shfl_xor_sync(0xffffffffu, v, o);
        if (threadIdx.x == 0) red[0] = v;
    }
    __syncthreads();
    float r = rsqrtf(red[0] * (1.f / HDIM) + 1e-6f);
    float* orow = out + (size_t)s * HDIM;
#pragma unroll
    for (int i = 0; i < 4; i++) { int id = threadIdx.x + i * 256; orow[id] = xr[id] * r * w[id]; }
}

// ---------------- per-head RMSNorm + RoPE ----------------
__global__ void rms_rope_kernel(const float* __restrict__ in, int stride,
                                const float* __restrict__ w,
                                const int* __restrict__ pos_ids,
                                float* __restrict__ out_nat,
                                float* __restrict__ present,
                                int nh) {
    int s = blockIdx.x;
    int warp = threadIdx.x >> 5, lane = threadIdx.x & 31;
    int h = blockIdx.y * 4 + warp;
    if (h >= nh) return;
    const float* x = in + (size_t)s * stride + h * HD;
    float x0 = x[lane], x1 = x[lane + 32];
    float ss = x0 * x0 + x1 * x1;
#pragma unroll
    for (int o = 16; o; o >>= 1) ss += __shfl_xor_sync(0xffffffffu, ss, o);
    float r = rsqrtf(ss * (1.f / HD) + 1e-6f);
    x0 = x0 * r * w[lane];
    x1 = x1 * r * w[lane + 32];
    float pos = (float)pos_ids[s];
    float invf = expf(-((float)lane * (1.f / 32.f)) * 9.210340371976184f);
    float ang = pos * invf;
    float c, sn;
    sincosf(ang, &sn, &c);
    float o0 = x0 * c - x1 * sn;
    float o1 = x1 * c + x0 * sn;
    if (out_nat) {
        float* op = out_nat + (size_t)s * stride + h * HD;
        op[lane] = o0; op[lane + 32] = o1;
    }
    if (present) {
        float* pp = present + ((size_t)h * SEQ + s) * HD;
        pp[lane] = o0; pp[lane + 32] = o1;
    }
}

// ---------------- copy V into present_values [NKV,S,HD] ----------------
__global__ void copy_v_kernel(const float* __restrict__ qkv, float* __restrict__ pv) {
    int s = blockIdx.x;
    int t = threadIdx.x;
    int kv = t >> 6, d = t & 63;
    pv[((size_t)kv * SEQ + s) * HD + d] = qkv[(size_t)s * QKVN + 1280 + t];
}

// ---------------- tensor-core flash attention ----------------
// 64 q-rows x 64 kv per tile, 4 warps (each m16), 128 threads.
// Q from g_qkv (stride QKVN, scaled by 0.125, reg-resident hi/lo frags),
// K from present [kvh][s][d], V from present [kvh][s][d] (transposed to smem).
__global__ __launch_bounds__(128) void attn_mma_kernel(const float* __restrict__ q,
                                                       const float* __restrict__ Kp,
                                                       const float* __restrict__ Vp,
                                                       float* __restrict__ o) {
    __shared__ uint32_t KHi[64 * 36], KLo[64 * 36];
    __shared__ uint32_t VtHi[64 * 36], VtLo[64 * 36];

    int qt = blockIdx.x, h = blockIdx.y, kvh = h >> 2;
    int tid = threadIdx.x, w = tid >> 5, lane = tid & 31;
    int gid = lane >> 2, tig = lane & 3;

    const float* K = Kp + (size_t)kvh * SEQ * HD;
    const float* V = Vp + (size_t)kvh * SEQ * HD;

    // --- Q fragments (hi/lo), scaled ---
    uint32_t qh[4][4], ql[4][4];
    {
        int r0 = qt * 64 + w * 16 + gid;
        const float* q0 = q + (size_t)r0 * QKVN + h * HD;
        const float* q1 = q0 + 8 * QKVN;
#pragma unroll
        for (int c = 0; c < 4; c++) {
            float2 x0 = *(const float2*)(q0 + c * 16 + tig * 2);
            float2 x1 = *(const float2*)(q1 + c * 16 + tig * 2);
            float2 x2 = *(const float2*)(q0 + c * 16 + 8 + tig * 2);
            float2 x3 = *(const float2*)(q1 + c * 16 + 8 + tig * 2);
            split2(x0.x * 0.125f, x0.y * 0.125f, qh[c][0], ql[c][0]);
            split2(x1.x * 0.125f, x1.y * 0.125f, qh[c][1], ql[c][1]);
            split2(x2.x * 0.125f, x2.y * 0.125f, qh[c][2], ql[c][2]);
            split2(x3.x * 0.125f, x3.y * 0.125f, qh[c][3], ql[c][3]);
        }
    }

    float m0 = -1e30f, m1 = -1e30f, l0 = 0.f, l1 = 0.f;
    float acc[8][4];
#pragma unroll
    for (int nb = 0; nb < 8; nb++)
#pragma unroll
        for (int r = 0; r < 4; r++) acc[nb][r] = 0.f;

    int r0loc = w * 16 + gid, r1loc = r0loc + 8;

    for (int kt = 0; kt <= qt; kt++) {
        // ---- load K tile (pairs along d) ----
#pragma unroll
        for (int i = 0; i < 8; i++) {
            int idx = tid + i * 128;
            int row = idx >> 4, dg = idx & 15;
            float4 kv4 = *(const float4*)&K[(size_t)(kt * 64 + row) * HD + dg * 4];
            uint32_t h0, l0_, h1, l1_;
            split2(kv4.x, kv4.y, h0, l0_);
            split2(kv4.z, kv4.w, h1, l1_);
            *(uint2*)&KHi[row * 36 + dg * 2] = make_uint2(h0, h1);
            *(uint2*)&KLo[row * 36 + dg * 2] = make_uint2(l0_, l1_);
        }
        // ---- load V tile transposed (pairs along s) ----
#pragma unroll
        for (int i = 0; i < 4; i++) {
            int idx = tid + i * 128;
            int sp = idx >> 4, dg = idx & 15;
            const float* vb = &V[(size_t)(kt * 64 + sp * 2) * HD + dg * 4];
            float4 v0 = *(const float4*)vb;
            float4 v1 = *(const float4*)(vb + HD);
            float a0[4] = {v0.x, v0.y, v0.z, v0.w};
            float a1[4] = {v1.x, v1.y, v1.z, v1.w};
#pragma unroll
            for (int j = 0; j < 4; j++) {
                uint32_t hh, ll;
                split2(a0[j], a1[j], hh, ll);
                VtHi[(dg * 4 + j) * 36 + sp] = hh;
                VtLo[(dg * 4 + j) * 36 + sp] = ll;
            }
        }
        __syncthreads();

        // ---- scores: sc[nb][4] = Q*K^T (3-term bf16) ----
        float sc[8][4];
#pragma unroll
        for (int nb = 0; nb < 8; nb++)
#pragma unroll
            for (int r = 0; r < 4; r++) sc[nb][r] = 0.f;

#pragma unroll
        for (int c = 0; c < 4; c++) {
#pragma unroll
            for (int nb = 0; nb < 8; nb++) {
                int srow = (nb * 8 + gid) * 36 + c * 8 + tig;
                uint32_t bh[2] = {KHi[srow], KHi[srow + 4]};
                uint32_t bl[2] = {KLo[srow], KLo[srow + 4]};
                mma_bf16(sc[nb], qh[c], bl);
                mma_bf16(sc[nb], ql[c], bh);
                mma_bf16(sc[nb], qh[c], bh);
            }
        }

        // ---- causal mask (diag tile only) ----
        if (kt == qt) {
#pragma unroll
            for (int nb = 0; nb < 8; nb++) {
#pragma unroll
                for (int j = 0; j < 2; j++) {
                    int col = nb * 8 + tig * 2 + j;
                    if (col > r0loc) sc[nb][j] = -1e30f;
                    if (col > r1loc) sc[nb][2 + j] = -1e30f;
                }
            }
        }

        // ---- online softmax (rows r0, r1) ----
        float mx0 = -1e30f, mx1 = -1e30f;
#pragma unroll
        for (int nb = 0; nb < 8; nb++) {
            mx0 = fmaxf(mx0, fmaxf(sc[nb][0], sc[nb][1]));
            mx1 = fmaxf(mx1, fmaxf(sc[nb][2], sc[nb][3]));
        }
        mx0 = fmaxf(mx0, __shfl_xor_sync(0xffffffffu, mx0, 1));
        mx0 = fmaxf(mx0, __shfl_xor_sync(0xffffffffu, mx0, 2));
        mx1 = fmaxf(mx1, __shfl_xor_sync(0xffffffffu, mx1, 1));
        mx1 = fmaxf(mx1, __shfl_xor_sync(0xffffffffu, mx1, 2));
        float mn0 = fmaxf(m0, mx0), mn1 = fmaxf(m1, mx1);
        float al0 = __expf(m0 - mn0), al1 = __expf(m1 - mn1);
        float s0 = 0.f, s1 = 0.f;
#pragma unroll
        for (int nb = 0; nb < 8; nb++) {
            sc[nb][0] = __expf(sc[nb][0] - mn0);
            sc[nb][1] = __expf(sc[nb][1] - mn0);
            sc[nb][2] = __expf(sc[nb][2] - mn1);
            sc[nb][3] = __expf(sc[nb][3] - mn1);
            s0 += sc[nb][0] + sc[nb][1];
            s1 += sc[nb][2] + sc[nb][3];
        }
        s0 += __shfl_xor_sync(0xffffffffu, s0, 1);
        s0 += __shfl_xor_sync(0xffffffffu, s0, 2);
        s1 += __shfl_xor_sync(0xffffffffu, s1, 1);
        s1 += __shfl_xor_sync(0xffffffffu, s1, 2);
        l0 = l0 * al0 + s0; m0 = mn0;
        l1 = l1 * al1 + s1; m1 = mn1;
#pragma unroll
        for (int nb = 0; nb < 8; nb++) {
            acc[nb][0] *= al0; acc[nb][1] *= al0;
            acc[nb][2] *= al1; acc[nb][3] *= al1;
        }

        // ---- P @ V (3-term bf16) ----
#pragma unroll
        for (int c = 0; c < 4; c++) {
            uint32_t ah[4], al_[4];
            split2(sc[2 * c][0],     sc[2 * c][1],     ah[0], al_[0]);
            split2(sc[2 * c][2],     sc[2 * c][3],     ah[1], al_[1]);
            split2(sc[2 * c + 1][0], sc[2 * c + 1][1], ah[2], al_[2]);
            split2(sc[2 * c + 1][2], sc[2 * c + 1][3], ah[3], al_[3]);
#pragma unroll
            for (int nb = 0; nb < 8; nb++) {
                int drow = (nb * 8 + gid) * 36 + c * 8 + tig;
                uint32_t bh[2] = {VtHi[drow], VtHi[drow + 4]};
                uint32_t bl[2] = {VtLo[drow], VtLo[drow + 4]};
                mma_bf16(acc[nb], ah, bl);
                mma_bf16(acc[nb], al_, bh);
                mma_bf16(acc[nb], ah, bh);
            }
        }
        __syncthreads();
    }

    // ---- epilogue ----
    float inv0 = 1.f / l0, inv1 = 1.f / l1;
    int row0 = qt * 64 + w * 16 + gid;
#pragma unroll
    for (int nb = 0; nb < 8; nb++) {
        int col = h * HD + nb * 8 + tig * 2;
        *(float2*)&o[(size_t)row0 * (NH * HD) + col] =
            make_float2(acc[nb][0] * inv0, acc[nb][1] * inv0);
        *(float2*)&o[(size_t)(row0 + 8) * (NH * HD) + col] =
            make_float2(acc[nb][2] * inv1, acc[nb][3] * inv1);
    }
}

// ---------------- silu(g) * u ----------------
__global__ void silu_mul_kernel(const float* __restrict__ gu, float* __restrict__ out, int n) {
    int i = blockIdx.x * 256 + threadIdx.x;
    if (i < n) {
        int s = i >> 12, c = i & 4095;
        float x = gu[(size_t)s * GUN + c];
        float u = gu[(size_t)s * GUN + IDIM + c];
        out[i] = x / (1.f + expf(-x)) * u;
    }
}

// ---------------- host launch ----------------
extern "C" void kernel_launch(void* const* d_in, const int* in_sizes, int n_in,
                              void* d_out, int out_size) {
    (void)in_sizes; (void)n_in; (void)out_size;

    static bool init = false;
    static float *p_h, *p_norm, *p_qkv, *p_att, *p_gu, *p_act;
    static uint32_t *p_wqkv, *p_wo, *p_wgu, *p_wdown, *p_wlm;
    if (!init) {
        cudaGetSymbolAddress((void**)&p_h, g_h);
        cudaGetSymbolAddress((void**)&p_norm, g_norm);
        cudaGetSymbolAddress((void**)&p_qkv, g_qkv);
        cudaGetSymbolAddress((void**)&p_att, g_att);
        cudaGetSymbolAddress((void**)&p_gu, g_gu);
        cudaGetSymbolAddress((void**)&p_act, g_act);
        cudaGetSymbolAddress((void**)&p_wqkv, wp_qkv);
        cudaGetSymbolAddress((void**)&p_wo, wp_o);
        cudaGetSymbolAddress((void**)&p_wgu, wp_gu);
        cudaGetSymbolAddress((void**)&p_wdown, wp_down);
        cudaGetSymbolAddress((void**)&p_wlm, wp_lm);
        init = true;
    }

    const int*   ids    = (const int*)d_in[0];
    const int*   pos    = (const int*)d_in[1];
    const float* audio  = (const float*)d_in[2];
    const int*   aoff   = (const int*)d_in[3];
    const float* embw   = (const float*)d_in[4];
    const float* q_w    = (const float*)d_in[5];
    const float* k_w    = (const float*)d_in[6];
    const float* v_w    = (const float*)d_in[7];
    const float* o_w    = (const float*)d_in[8];
    const float* qn_w   = (const float*)d_in[9];
    const float* kn_w   = (const float*)d_in[10];
    const float* ln1_w  = (const float*)d_in[11];
    const float* ln2_w  = (const float*)d_in[12];
    const float* gate_w = (const float*)d_in[13];
    const float* up_w   = (const float*)d_in[14];
    const float* down_w = (const float*)d_in[15];
    const float* norm_w = (const float*)d_in[16];
    const float* lm_w   = (const float*)d_in[17];

    float* out    = (float*)d_out;
    float* logits = out;
    float* pk     = out + (size_t)SEQ * VOCAB;
    float* pv     = pk + (size_t)NLAYER * NKV * SEQ * HD;

    const int BIG = 1 << 30;

    for (int l = 0; l < NLAYER; l++) {
        prep_w_kernel<<<dim3(QKVN / 128, HDIM / 32), 256>>>(
            q_w + (size_t)l * HDIM * (NH * HD), NH * HD,
            k_w + (size_t)l * HDIM * (NKV * HD), NKV * HD,
            v_w + (size_t)l * HDIM * (NKV * HD), NKV * HD,
            NH * HD, NH * HD + NKV * HD,
            p_wqkv + (size_t)l * HDIM * QKVN);
        prep_w_kernel<<<dim3(HDIM / 128, HDIM / 32), 256>>>(
            o_w + (size_t)l * HDIM * HDIM, HDIM, o_w, HDIM, o_w, HDIM, BIG, BIG,
            p_wo + (size_t)l * HDIM * HDIM);
        prep_w_kernel<<<dim3(GUN / 128, HDIM / 32), 256>>>(
            gate_w + (size_t)l * HDIM * IDIM, IDIM,
            up_w + (size_t)l * HDIM * IDIM, IDIM,
            up_w, IDIM, IDIM, BIG,
            p_wgu + (size_t)l * HDIM * GUN);
        prep_w_kernel<<<dim3(HDIM / 128, IDIM / 32), 256>>>(
            down_w + (size_t)l * IDIM * HDIM, HDIM, down_w, HDIM, down_w, HDIM, BIG, BIG,
            p_wdown + (size_t)l * IDIM * HDIM);
    }
    prep_w_kernel<<<dim3(VOCAB / 128, HDIM / 32), 256>>>(
        lm_w, VOCAB, lm_w, VOCAB, lm_w, VOCAB, BIG, BIG, p_wlm);

    embed_scatter_kernel<<<SEQ, 256>>>(ids, embw, audio, aoff, p_h);

    for (int l = 0; l < NLAYER; l++) {
        rmsnorm_kernel<<<SEQ, 256>>>(p_h, ln1_w + (size_t)l * HDIM, p_norm);

        gemm_bf16x2_kernel<<<dim3(QKVN / 128, SEQ / 128), 256>>>(
            p_norm, p_wqkv + (size_t)l * HDIM * QKVN, nullptr, p_qkv, SEQ, QKVN, HDIM);

        rms_rope_kernel<<<dim3(SEQ, 4), 128>>>(p_qkv, QKVN, qn_w + (size_t)l * HD, pos,
                                               p_qkv, nullptr, NH);
        rms_rope_kernel<<<dim3(SEQ, 1), 128>>>(p_qkv + NH * HD, QKVN, kn_w + (size_t)l * HD, pos,
                                               nullptr, pk + (size_t)l * NKV * SEQ * HD, NKV);
        copy_v_kernel<<<SEQ, 256>>>(p_qkv, pv + (size_t)l * NKV * SEQ * HD);

        attn_mma_kernel<<<dim3(SEQ / 64, NH), 128>>>(
            p_qkv, pk + (size_t)l * NKV * SEQ * HD, pv + (size_t)l * NKV * SEQ * HD, p_att);

        gemm_bf16x2_kernel<<<dim3(HDIM / 128, SEQ / 128), 256>>>(
            p_att, p_wo + (size_t)l * HDIM * HDIM, p_h, p_h, SEQ, HDIM, HDIM);

        rmsnorm_kernel<<<SEQ, 256>>>(p_h, ln2_w + (size_t)l * HDIM, p_norm);

        gemm_bf16x2_kernel<<<dim3(GUN / 128, SEQ / 128), 256>>>(
            p_norm, p_wgu + (size_t)l * HDIM * GUN, nullptr, p_gu, SEQ, GUN, HDIM);

        silu_mul_kernel<<<(SEQ * IDIM) / 256, 256>>>(p_gu, p_act, SEQ * IDIM);

        gemm_bf16x2_kernel<<<dim3(HDIM / 128, SEQ / 128), 256>>>(
            p_act, p_wdown + (size_t)l * IDIM * HDIM, p_h, p_h, SEQ, HDIM, IDIM);
    }

    rmsnorm_kernel<<<SEQ, 256>>>(p_h, norm_w, p_norm);
    gemm_bf16x2_kernel<<<dim3(VOCAB / 128, SEQ / 128), 256>>>(
        p_norm, p_wlm, nullptr, logits, SEQ, VOCAB, HDIM);
}

// round 11
// speedup vs baseline: 1.5477x; 1.5477x over previous
#include <cuda_runtime.h>
#include <cuda_bf16.h>
#include <stdint.h>
#include <math.h>

#define SEQ 2048
#define HDIM 1024
#define NLAYER 4
#define NH 16
#define NKV 4
#define HD 64
#define IDIM 4096
#define VOCAB 32000
#define QKVN 1536
#define GUN 8192

// ---------------- scratch ----------------
__device__ float g_h[SEQ * HDIM];
__device__ float g_norm[SEQ * HDIM];
__device__ float g_qkv[SEQ * QKVN];
__device__ float g_att[SEQ * NH * HD];
__device__ float g_gu[SEQ * GUN];
__device__ float g_act[SEQ * IDIM];

__device__ uint32_t wp_qkv[NLAYER * HDIM * QKVN];
__device__ uint32_t wp_o[NLAYER * HDIM * HDIM];
__device__ uint32_t wp_gu[NLAYER * HDIM * GUN];
__device__ uint32_t wp_down[NLAYER * IDIM * HDIM];
__device__ uint32_t wp_lm[HDIM * VOCAB];

// pre-split attention operands (per current layer)
__device__ uint32_t g_ks[NKV * SEQ * 64];          // [kvh][s][hi(32)|lo(32)] d-pairs
__device__ uint32_t g_vthi[NKV * 64 * (SEQ / 2)];  // [kvh][d][sp] s-pairs hi
__device__ uint32_t g_vtlo[NKV * 64 * (SEQ / 2)];  // lo

// ---------------- helpers ----------------
__device__ __forceinline__ void split2(float x, float y, uint32_t& hi, uint32_t& lo) {
    __nv_bfloat162 h = __floats2bfloat162_rn(x, y);
    hi = *(uint32_t*)&h;
    __nv_bfloat162 l = __floats2bfloat162_rn(x - __bfloat162float(h.x),
                                             y - __bfloat162float(h.y));
    lo = *(uint32_t*)&l;
}

__device__ __forceinline__ void mma_bf16(float* c, const uint32_t* a, const uint32_t* b) {
    asm volatile(
        "mma.sync.aligned.m16n8k16.row.col.f32.bf16.bf16.f32 "
        "{%0,%1,%2,%3}, {%4,%5,%6,%7}, {%8,%9}, {%0,%1,%2,%3};"
        : "+f"(c[0]), "+f"(c[1]), "+f"(c[2]), "+f"(c[3])
        : "r"(a[0]), "r"(a[1]), "r"(a[2]), "r"(a[3]), "r"(b[0]), "r"(b[1]));
}

__device__ __forceinline__ void cp_async16(void* smem, const void* gmem) {
    uint32_t s = (uint32_t)__cvta_generic_to_shared(smem);
    asm volatile("cp.async.cg.shared.global [%0], [%1], 16;" :: "r"(s), "l"(gmem));
}
#define CP_COMMIT() asm volatile("cp.async.commit_group;")
#define CP_WAIT0()  asm volatile("cp.async.wait_group 0;")

// ---------------- weight prep ----------------
__global__ void prep_w_kernel(const float* __restrict__ s0, int st0,
                              const float* __restrict__ s1, int st1,
                              const float* __restrict__ s2, int st2,
                              int n1, int n2, uint32_t* __restrict__ out) {
    int kt = blockIdx.y, nt = blockIdx.x, NT = gridDim.x;
    int t = threadIdx.x;
#pragma unroll
    for (int it = 0; it < 4; it++) {
        int slot = it * 256 + t;
        int lane = slot & 31, in = (slot >> 5) & 15, ik = slot >> 9;
        int g = lane >> 2, c = lane & 3;
        int n = nt * 128 + in * 8 + g;
        int kb = kt * 32 + ik * 16 + 2 * c;
        const float* src; int nn; int st;
        if (n >= n2)      { src = s2; nn = n - n2; st = st2; }
        else if (n >= n1) { src = s1; nn = n - n1; st = st1; }
        else              { src = s0; nn = n;      st = st0; }
        float x0 = src[(size_t)(kb + 0) * st + nn];
        float x1 = src[(size_t)(kb + 1) * st + nn];
        float x8 = src[(size_t)(kb + 8) * st + nn];
        float x9 = src[(size_t)(kb + 9) * st + nn];
        uint4 o;
        uint32_t l01, l89;
        split2(x0, x1, o.x, l01);
        split2(x8, x9, o.y, l89);
        o.z = l01; o.w = l89;
        *(uint4*)&out[((size_t)((size_t)kt * NT + nt) * 1024 + slot) * 4] = o;
    }
}

// ---------------- bf16x2 (3-term) tensor-core GEMM ----------------
__global__ __launch_bounds__(256) void gemm_bf16x2_kernel(
    const float* __restrict__ A, const uint32_t* __restrict__ Bp,
    const float* __restrict__ Res, float* __restrict__ C,
    int M, int N, int K) {
    __shared__ uint32_t Asm[2][4096];
    __shared__ uint32_t Bsm[2][4096];

    int tid = threadIdx.x, lane = tid & 31, warp = tid >> 5;
    int wm = warp >> 2, wn = warp & 3;
    int bm = blockIdx.y * 128, bnx = blockIdx.x;
    int NT = N >> 7, KT = K >> 5;

    float acc[4][4][4];
#pragma unroll
    for (int im = 0; im < 4; im++)
#pragma unroll
        for (int in = 0; in < 4; in++)
#pragma unroll
            for (int r = 0; r < 4; r++) acc[im][in][r] = 0.f;

    float4 pa[4];

#define LDGA(kt)                                                                     \
    {                                                                                \
        _Pragma("unroll")                                                            \
        for (int i = 0; i < 4; i++) {                                                \
            int f = tid + i * 256;                                                   \
            pa[i] = *(const float4*)(A + (size_t)(bm + (f >> 3)) * K + (kt) * 32 + ((f & 7) << 2)); \
        }                                                                            \
    }

#define CPB(kt, st)                                                                  \
    {                                                                                \
        _Pragma("unroll")                                                            \
        for (int i = 0; i < 4; i++) {                                                \
            int slot = tid + i * 256;                                                \
            cp_async16(&Bsm[st][slot * 4],                                           \
                       Bp + ((size_t)((size_t)(kt) * NT + bnx) * 1024 + slot) * 4);  \
        }                                                                            \
    }

#define STSA(st)                                                                     \
    {                                                                                \
        _Pragma("unroll")                                                            \
        for (int i = 0; i < 4; i++) {                                                \
            int f = tid + i * 256;                                                   \
            int row = f >> 3, k0 = (f & 7) << 2;                                     \
            int ik = k0 >> 4, h = (k0 >> 3) & 1, c0 = (k0 & 7) >> 1;                 \
            int im = row >> 4, reg = ((row >> 3) & 1) + (h << 1);                    \
            int lane0 = ((row & 7) << 2) + c0;                                       \
            float4 v = pa[i];                                                        \
            uint32_t h01, l01, h23, l23;                                             \
            split2(v.x, v.y, h01, l01);                                              \
            split2(v.z, v.w, h23, l23);                                              \
            int baseHi = ((ik * 8 + im) * 2 + 0) * 32;                               \
            int baseLo = ((ik * 8 + im) * 2 + 1) * 32;                               \
            Asm[st][(baseHi + lane0) * 4 + reg]     = h01;                           \
            Asm[st][(baseHi + lane0 + 1) * 4 + reg] = h23;                           \
            Asm[st][(baseLo + lane0) * 4 + reg]     = l01;                           \
            Asm[st][(baseLo + lane0 + 1) * 4 + reg] = l23;                           \
        }                                                                            \
    }

#define COMPUTE(st)                                                                  \
    {                                                                                \
        _Pragma("unroll")                                                            \
        for (int ik = 0; ik < 2; ik++) {                                             \
            uint32_t ah[4][4], al[4][4], bh[4][2], bl[4][2];                         \
            _Pragma("unroll")                                                        \
            for (int im = 0; im < 4; im++) {                                         \
                *(uint4*)ah[im] = *(const uint4*)&Asm[st][(((ik * 8 + wm * 4 + im) * 2 + 0) * 32 + lane) * 4]; \
                *(uint4*)al[im] = *(const uint4*)&Asm[st][(((ik * 8 + wm * 4 + im) * 2 + 1) * 32 + lane) * 4]; \
            }                                                                        \
            _Pragma("unroll")                                                        \
            for (int in = 0; in < 4; in++) {                                         \
                uint4 qv = *(const uint4*)&Bsm[st][((ik * 16 + wn * 4 + in) * 32 + lane) * 4]; \
                bh[in][0] = qv.x; bh[in][1] = qv.y;                                  \
                bl[in][0] = qv.z; bl[in][1] = qv.w;                                  \
            }                                                                        \
            _Pragma("unroll")                                                        \
            for (int im = 0; im < 4; im++)                                           \
                _Pragma("unroll")                                                    \
                for (int in = 0; in < 4; in++) {                                     \
                    mma_bf16(acc[im][in], ah[im], bl[in]);                           \
                    mma_bf16(acc[im][in], al[im], bh[in]);                           \
                    mma_bf16(acc[im][in], ah[im], bh[in]);                           \
                }                                                                    \
        }                                                                            \
    }

    LDGA(0);
    CPB(0, 0); CP_COMMIT();
    STSA(0);
    CP_WAIT0();
    __syncthreads();

    for (int kt = 0; kt < KT; kt++) {
        int st = kt & 1;
        if (kt + 1 < KT) { LDGA(kt + 1); CPB(kt + 1, st ^ 1); CP_COMMIT(); }
        COMPUTE(st);
        if (kt + 1 < KT) { STSA(st ^ 1); CP_WAIT0(); }
        __syncthreads();
    }

    int gid = lane >> 2, tig = lane & 3;
#pragma unroll
    for (int im = 0; im < 4; im++) {
#pragma unroll
        for (int in = 0; in < 4; in++) {
            int row0 = bm + wm * 64 + im * 16 + gid;
            int col = bnx * 128 + wn * 32 + in * 8 + tig * 2;
            float2 v0 = make_float2(acc[im][in][0], acc[im][in][1]);
            float2 v1 = make_float2(acc[im][in][2], acc[im][in][3]);
            if (Res) {
                float2 r0 = *(const float2*)(Res + (size_t)row0 * N + col);
                float2 r1 = *(const float2*)(Res + (size_t)(row0 + 8) * N + col);
                v0.x += r0.x; v0.y += r0.y;
                v1.x += r1.x; v1.y += r1.y;
            }
            *(float2*)(C + (size_t)row0 * N + col) = v0;
            *(float2*)(C + (size_t)(row0 + 8) * N + col) = v1;
        }
    }
#undef LDGA
#undef CPB
#undef STSA
#undef COMPUTE
}

// ---------------- embedding + audio scatter ----------------
__global__ void embed_scatter_kernel(const int* __restrict__ ids,
                                     const float* __restrict__ emb,
                                     const float* __restrict__ audio,
                                     const int* __restrict__ aoff,
                                     float* __restrict__ h) {
    int s = blockIdx.x;
    int off = aoff[0];
    const float* src;
    if (s >= off && s < off + 256) src = audio + (size_t)(s - off) * HDIM;
    else                           src = emb + (size_t)ids[s] * HDIM;
    float* dst = h + (size_t)s * HDIM;
    int i = threadIdx.x * 4;
    *(float4*)&dst[i] = *(const float4*)&src[i];
}

// ---------------- RMSNorm H=1024 ----------------
__global__ void rmsnorm_kernel(const float* __restrict__ x,
                               const float* __restrict__ w,
                               float* __restrict__ out) {
    int s = blockIdx.x;
    const float* xr = x + (size_t)s * HDIM;
    float ss = 0.f;
#pragma unroll
    for (int i = 0; i < 4; i++) { float v = xr[threadIdx.x + i * 256]; ss += v * v; }
    __shared__ float red[8];
#pragma unroll
    for (int o = 16; o; o >>= 1) ss += __shfl_xor_sync(0xffffffffu, ss, o);
    if ((threadIdx.x & 31) == 0) red[threadIdx.x >> 5] = ss;
    __syncthreads();
    if (threadIdx.x < 32) {
        float v = (threadIdx.x < 8) ? red[threadIdx.x] : 0.f;
#pragma unroll
        for (int o = 4; o; o >>= 1) v += __shfl_xor_sync(0xffffffffu, v, o);
        if (threadIdx.x == 0) red[0] = v;
    }
    __syncthreads();
    float r = rsqrtf(red[0] * (1.f / HDIM) + 1e-6f);
    float* orow = out + (size_t)s * HDIM;
#pragma unroll
    for (int i = 0; i < 4; i++) { int id = threadIdx.x + i * 256; orow[id] = xr[id] * r * w[id]; }
}

// ---------------- per-head RMSNorm + RoPE ----------------
__global__ void rms_rope_kernel(const float* __restrict__ in, int stride,
                                const float* __restrict__ w,
                                const int* __restrict__ pos_ids,
                                float* __restrict__ out_nat,
                                float* __restrict__ present,
                                int nh) {
    int s = blockIdx.x;
    int warp = threadIdx.x >> 5, lane = threadIdx.x & 31;
    int h = blockIdx.y * 4 + warp;
    if (h >= nh) return;
    const float* x = in + (size_t)s * stride + h * HD;
    float x0 = x[lane], x1 = x[lane + 32];
    float ss = x0 * x0 + x1 * x1;
#pragma unroll
    for (int o = 16; o; o >>= 1) ss += __shfl_xor_sync(0xffffffffu, ss, o);
    float r = rsqrtf(ss * (1.f / HD) + 1e-6f);
    x0 = x0 * r * w[lane];
    x1 = x1 * r * w[lane + 32];
    float pos = (float)pos_ids[s];
    float invf = expf(-((float)lane * (1.f / 32.f)) * 9.210340371976184f);
    float ang = pos * invf;
    float c, sn;
    sincosf(ang, &sn, &c);
    float o0 = x0 * c - x1 * sn;
    float o1 = x1 * c + x0 * sn;
    if (out_nat) {
        float* op = out_nat + (size_t)s * stride + h * HD;
        op[lane] = o0; op[lane + 32] = o1;
    }
    if (present) {
        float* pp = present + ((size_t)h * SEQ + s) * HD;
        pp[lane] = o0; pp[lane + 32] = o1;
    }
}

// ---------------- copy V into present_values [NKV,S,HD] ----------------
__global__ void copy_v_kernel(const float* __restrict__ qkv, float* __restrict__ pv) {
    int s = blockIdx.x;
    int t = threadIdx.x;
    int kv = t >> 6, d = t & 63;
    pv[((size_t)kv * SEQ + s) * HD + d] = qkv[(size_t)s * QKVN + 1280 + t];
}

// ---------------- split K: present [kvh][s][d] -> [kvh][s][hi32|lo32] ----------------
__global__ void split_k_kernel(const float* __restrict__ pk, uint32_t* __restrict__ ks) {
    int p = blockIdx.x * 256 + threadIdx.x;       // NKV*SEQ*32
    int row = p >> 5, dg = p & 31;
    float2 v = *(const float2*)&pk[(size_t)row * HD + dg * 2];
    uint32_t hi, lo;
    split2(v.x, v.y, hi, lo);
    ks[(size_t)row * 64 + dg] = hi;
    ks[(size_t)row * 64 + 32 + dg] = lo;
}

// ---------------- split V^T: present [kvh][s][d] -> [kvh][d][sp] (s-pairs) ----------------
__global__ void split_vt_kernel(const float* __restrict__ pv,
                                uint32_t* __restrict__ vthi, uint32_t* __restrict__ vtlo) {
    int p = blockIdx.x * 256 + threadIdx.x;       // NKV*1024*64
    int kvh = p >> 16, rem = p & 65535;
    int sp = rem >> 6, d = rem & 63;
    float v0 = pv[((size_t)kvh * SEQ + 2 * sp) * HD + d];
    float v1 = pv[((size_t)kvh * SEQ + 2 * sp + 1) * HD + d];
    uint32_t hi, lo;
    split2(v0, v1, hi, lo);
    vthi[((size_t)kvh * 64 + d) * (SEQ / 2) + sp] = hi;
    vtlo[((size_t)kvh * 64 + d) * (SEQ / 2) + sp] = lo;
}

// ---------------- tensor-core flash attention (pre-split K/V, cp.async) ----------------
// 128 q-rows per block (8 warps x m16), 64 kv per tile.
__global__ __launch_bounds__(256) void attn_mma_kernel(const float* __restrict__ q,
                                                       const uint32_t* __restrict__ Ks,
                                                       const uint32_t* __restrict__ Vthi,
                                                       const uint32_t* __restrict__ Vtlo,
                                                       float* __restrict__ o) {
    __shared__ uint32_t KHi[64 * 36], KLo[64 * 36];
    __shared__ uint32_t VHi[64 * 36], VLo[64 * 36];

    int qb = blockIdx.x, h = blockIdx.y, kvh = h >> 2;
    int tid = threadIdx.x, w = tid >> 5, lane = tid & 31;
    int gid = lane >> 2, tig = lane & 3;

    // --- Q fragments (hi/lo), scaled by 1/8 ---
    uint32_t qh[4][4], ql[4][4];
    int rmin = qb * 128 + w * 16;
    {
        const float* q0 = q + (size_t)(rmin + gid) * QKVN + h * HD;
        const float* q1 = q0 + 8 * QKVN;
#pragma unroll
        for (int c = 0; c < 4; c++) {
            float2 x0 = *(const float2*)(q0 + c * 16 + tig * 2);
            float2 x1 = *(const float2*)(q1 + c * 16 + tig * 2);
            float2 x2 = *(const float2*)(q0 + c * 16 + 8 + tig * 2);
            float2 x3 = *(const float2*)(q1 + c * 16 + 8 + tig * 2);
            split2(x0.x * 0.125f, x0.y * 0.125f, qh[c][0], ql[c][0]);
            split2(x1.x * 0.125f, x1.y * 0.125f, qh[c][1], ql[c][1]);
            split2(x2.x * 0.125f, x2.y * 0.125f, qh[c][2], ql[c][2]);
            split2(x3.x * 0.125f, x3.y * 0.125f, qh[c][3], ql[c][3]);
        }
    }

    float m0 = -1e30f, m1 = -1e30f, l0 = 0.f, l1 = 0.f;
    float acc[8][4];
#pragma unroll
    for (int nb = 0; nb < 8; nb++)
#pragma unroll
        for (int r = 0; r < 4; r++) acc[nb][r] = 0.f;

    int ktend = 2 * qb + 1;
    for (int kt = 0; kt <= ktend; kt++) {
        // ---- cp.async tile loads ----
#pragma unroll
        for (int i = 0; i < 4; i++) {
            int c0 = tid + i * 256;
            int row = c0 >> 4, part = c0 & 15;
            const uint32_t* src = Ks + ((size_t)(kvh * SEQ + kt * 64 + row)) * 64
                                  + ((part >> 3) * 32) + ((part & 7) * 4);
            uint32_t* dst = ((part >> 3) ? KLo : KHi) + row * 36 + (part & 7) * 4;
            cp_async16(dst, src);
        }
#pragma unroll
        for (int i = 0; i < 4; i++) {
            int c0 = tid + i * 256;
            int d = c0 >> 4, part = c0 & 15;
            const uint32_t* src = ((part >> 3) ? Vtlo : Vthi)
                                  + ((size_t)kvh * 64 + d) * (SEQ / 2) + kt * 32 + (part & 7) * 4;
            uint32_t* dst = ((part >> 3) ? VLo : VHi) + d * 36 + (part & 7) * 4;
            cp_async16(dst, src);
        }
        CP_COMMIT();
        CP_WAIT0();
        __syncthreads();

        bool skip = (kt * 64 > rmin + 15);
        if (!skip) {
            // ---- scores ----
            float sc[8][4];
#pragma unroll
            for (int nb = 0; nb < 8; nb++)
#pragma unroll
                for (int r = 0; r < 4; r++) sc[nb][r] = 0.f;

#pragma unroll
            for (int c = 0; c < 4; c++) {
#pragma unroll
                for (int nb = 0; nb < 8; nb++) {
                    int srow = (nb * 8 + gid) * 36 + c * 8 + tig;
                    uint32_t bh[2] = {KHi[srow], KHi[srow + 4]};
                    uint32_t bl[2] = {KLo[srow], KLo[srow + 4]};
                    mma_bf16(sc[nb], qh[c], bl);
                    mma_bf16(sc[nb], ql[c], bh);
                    mma_bf16(sc[nb], qh[c], bh);
                }
            }

            // ---- causal mask ----
            if (kt * 64 + 63 > rmin) {
                int r0 = rmin + gid, r1 = rmin + 8 + gid;
#pragma unroll
                for (int nb = 0; nb < 8; nb++) {
#pragma unroll
                    for (int j = 0; j < 2; j++) {
                        int col = kt * 64 + nb * 8 + tig * 2 + j;
                        if (col > r0) sc[nb][j] = -1e30f;
                        if (col > r1) sc[nb][2 + j] = -1e30f;
                    }
                }
            }

            // ---- online softmax ----
            float mx0 = -1e30f, mx1 = -1e30f;
#pragma unroll
            for (int nb = 0; nb < 8; nb++) {
                mx0 = fmaxf(mx0, fmaxf(sc[nb][0], sc[nb][1]));
                mx1 = fmaxf(mx1, fmaxf(sc[nb][2], sc[nb][3]));
            }
            mx0 = fmaxf(mx0, __shfl_xor_sync(0xffffffffu, mx0, 1));
            mx0 = fmaxf(mx0, __shfl_xor_sync(0xffffffffu, mx0, 2));
            mx1 = fmaxf(mx1, __shfl_xor_sync(0xffffffffu, mx1, 1));
            mx1 = fmaxf(mx1, __shfl_xor_sync(0xffffffffu, mx1, 2));
            float mn0 = fmaxf(m0, mx0), mn1 = fmaxf(m1, mx1);
            float al0 = __expf(m0 - mn0), al1 = __expf(m1 - mn1);
            float s0 = 0.f, s1 = 0.f;
#pragma unroll
            for (int nb = 0; nb < 8; nb++) {
                sc[nb][0] = __expf(sc[nb][0] - mn0);
                sc[nb][1] = __expf(sc[nb][1] - mn0);
                sc[nb][2] = __expf(sc[nb][2] - mn1);
                sc[nb][3] = __expf(sc[nb][3] - mn1);
                s0 += sc[nb][0] + sc[nb][1];
                s1 += sc[nb][2] + sc[nb][3];
            }
            s0 += __shfl_xor_sync(0xffffffffu, s0, 1);
            s0 += __shfl_xor_sync(0xffffffffu, s0, 2);
            s1 += __shfl_xor_sync(0xffffffffu, s1, 1);
            s1 += __shfl_xor_sync(0xffffffffu, s1, 2);
            l0 = l0 * al0 + s0; m0 = mn0;
            l1 = l1 * al1 + s1; m1 = mn1;
#pragma unroll
            for (int nb = 0; nb < 8; nb++) {
                acc[nb][0] *= al0; acc[nb][1] *= al0;
                acc[nb][2] *= al1; acc[nb][3] *= al1;
            }

            // ---- P @ V ----
#pragma unroll
            for (int c = 0; c < 4; c++) {
                uint32_t ah[4], al_[4];
                split2(sc[2 * c][0],     sc[2 * c][1],     ah[0], al_[0]);
                split2(sc[2 * c][2],     sc[2 * c][3],     ah[1], al_[1]);
                split2(sc[2 * c + 1][0], sc[2 * c + 1][1], ah[2], al_[2]);
                split2(sc[2 * c + 1][2], sc[2 * c + 1][3], ah[3], al_[3]);
#pragma unroll
                for (int nb = 0; nb < 8; nb++) {
                    int drow = (nb * 8 + gid) * 36 + c * 8 + tig;
                    uint32_t bh[2] = {VHi[drow], VHi[drow + 4]};
                    uint32_t bl[2] = {VLo[drow], VLo[drow + 4]};
                    mma_bf16(acc[nb], ah, bl);
                    mma_bf16(acc[nb], al_, bh);
                    mma_bf16(acc[nb], ah, bh);
                }
            }
        }
        __syncthreads();
    }

    // ---- epilogue ----
    float inv0 = 1.f / l0, inv1 = 1.f / l1;
    int row0 = rmin + gid;
#pragma unroll
    for (int nb = 0; nb < 8; nb++) {
        int col = h * HD + nb * 8 + tig * 2;
        *(float2*)&o[(size_t)row0 * (NH * HD) + col] =
            make_float2(acc[nb][0] * inv0, acc[nb][1] * inv0);
        *(float2*)&o[(size_t)(row0 + 8) * (NH * HD) + col] =
            make_float2(acc[nb][2] * inv1, acc[nb][3] * inv1);
    }
}

// ---------------- silu(g) * u ----------------
__global__ void silu_mul_kernel(const float* __restrict__ gu, float* __restrict__ out, int n) {
    int i = blockIdx.x * 256 + threadIdx.x;
    if (i < n) {
        int s = i >> 12, c = i & 4095;
        float x = gu[(size_t)s * GUN + c];
        float u = gu[(size_t)s * GUN + IDIM + c];
        out[i] = x / (1.f + __expf(-x)) * u;
    }
}

// ---------------- host launch ----------------
extern "C" void kernel_launch(void* const* d_in, const int* in_sizes, int n_in,
                              void* d_out, int out_size) {
    (void)in_sizes; (void)n_in; (void)out_size;

    static bool init = false;
    static float *p_h, *p_norm, *p_qkv, *p_att, *p_gu, *p_act;
    static uint32_t *p_wqkv, *p_wo, *p_wgu, *p_wdown, *p_wlm;
    static uint32_t *p_ks, *p_vthi, *p_vtlo;
    if (!init) {
        cudaGetSymbolAddress((void**)&p_h, g_h);
        cudaGetSymbolAddress((void**)&p_norm, g_norm);
        cudaGetSymbolAddress((void**)&p_qkv, g_qkv);
        cudaGetSymbolAddress((void**)&p_att, g_att);
        cudaGetSymbolAddress((void**)&p_gu, g_gu);
        cudaGetSymbolAddress((void**)&p_act, g_act);
        cudaGetSymbolAddress((void**)&p_wqkv, wp_qkv);
        cudaGetSymbolAddress((void**)&p_wo, wp_o);
        cudaGetSymbolAddress((void**)&p_wgu, wp_gu);
        cudaGetSymbolAddress((void**)&p_wdown, wp_down);
        cudaGetSymbolAddress((void**)&p_wlm, wp_lm);
        cudaGetSymbolAddress((void**)&p_ks, g_ks);
        cudaGetSymbolAddress((void**)&p_vthi, g_vthi);
        cudaGetSymbolAddress((void**)&p_vtlo, g_vtlo);
        init = true;
    }

    const int*   ids    = (const int*)d_in[0];
    const int*   pos    = (const int*)d_in[1];
    const float* audio  = (const float*)d_in[2];
    const int*   aoff   = (const int*)d_in[3];
    const float* embw   = (const float*)d_in[4];
    const float* q_w    = (const float*)d_in[5];
    const float* k_w    = (const float*)d_in[6];
    const float* v_w    = (const float*)d_in[7];
    const float* o_w    = (const float*)d_in[8];
    const float* qn_w   = (const float*)d_in[9];
    const float* kn_w   = (const float*)d_in[10];
    const float* ln1_w  = (const float*)d_in[11];
    const float* ln2_w  = (const float*)d_in[12];
    const float* gate_w = (const float*)d_in[13];
    const float* up_w   = (const float*)d_in[14];
    const float* down_w = (const float*)d_in[15];
    const float* norm_w = (const float*)d_in[16];
    const float* lm_w   = (const float*)d_in[17];

    float* out    = (float*)d_out;
    float* logits = out;
    float* pk     = out + (size_t)SEQ * VOCAB;
    float* pv     = pk + (size_t)NLAYER * NKV * SEQ * HD;

    const int BIG = 1 << 30;

    for (int l = 0; l < NLAYER; l++) {
        prep_w_kernel<<<dim3(QKVN / 128, HDIM / 32), 256>>>(
            q_w + (size_t)l * HDIM * (NH * HD), NH * HD,
            k_w + (size_t)l * HDIM * (NKV * HD), NKV * HD,
            v_w + (size_t)l * HDIM * (NKV * HD), NKV * HD,
            NH * HD, NH * HD + NKV * HD,
            p_wqkv + (size_t)l * HDIM * QKVN);
        prep_w_kernel<<<dim3(HDIM / 128, HDIM / 32), 256>>>(
            o_w + (size_t)l * HDIM * HDIM, HDIM, o_w, HDIM, o_w, HDIM, BIG, BIG,
            p_wo + (size_t)l * HDIM * HDIM);
        prep_w_kernel<<<dim3(GUN / 128, HDIM / 32), 256>>>(
            gate_w + (size_t)l * HDIM * IDIM, IDIM,
            up_w + (size_t)l * HDIM * IDIM, IDIM,
            up_w, IDIM, IDIM, BIG,
            p_wgu + (size_t)l * HDIM * GUN);
        prep_w_kernel<<<dim3(HDIM / 128, IDIM / 32), 256>>>(
            down_w + (size_t)l * IDIM * HDIM, HDIM, down_w, HDIM, down_w, HDIM, BIG, BIG,
            p_wdown + (size_t)l * IDIM * HDIM);
    }
    prep_w_kernel<<<dim3(VOCAB / 128, HDIM / 32), 256>>>(
        lm_w, VOCAB, lm_w, VOCAB, lm_w, VOCAB, BIG, BIG, p_wlm);

    embed_scatter_kernel<<<SEQ, 256>>>(ids, embw, audio, aoff, p_h);

    for (int l = 0; l < NLAYER; l++) {
        float* pk_l = pk + (size_t)l * NKV * SEQ * HD;
        float* pv_l = pv + (size_t)l * NKV * SEQ * HD;

        rmsnorm_kernel<<<SEQ, 256>>>(p_h, ln1_w + (size_t)l * HDIM, p_norm);

        gemm_bf16x2_kernel<<<dim3(QKVN / 128, SEQ / 128), 256>>>(
            p_norm, p_wqkv + (size_t)l * HDIM * QKVN, nullptr, p_qkv, SEQ, QKVN, HDIM);

        rms_rope_kernel<<<dim3(SEQ, 4), 128>>>(p_qkv, QKVN, qn_w + (size_t)l * HD, pos,
                                               p_qkv, nullptr, NH);
        rms_rope_kernel<<<dim3(SEQ, 1), 128>>>(p_qkv + NH * HD, QKVN, kn_w + (size_t)l * HD, pos,
                                               nullptr, pk_l, NKV);
        copy_v_kernel<<<SEQ, 256>>>(p_qkv, pv_l);

        split_k_kernel<<<NKV * SEQ * 32 / 256, 256>>>(pk_l, p_ks);
        split_vt_kernel<<<NKV * 64 * (SEQ / 2) / 256, 256>>>(pv_l, p_vthi, p_vtlo);

        attn_mma_kernel<<<dim3(SEQ / 128, NH), 256>>>(p_qkv, p_ks, p_vthi, p_vtlo, p_att);

        gemm_bf16x2_kernel<<<dim3(HDIM / 128, SEQ / 128), 256>>>(
            p_att, p_wo + (size_t)l * HDIM * HDIM, p_h, p_h, SEQ, HDIM, HDIM);

        rmsnorm_kernel<<<SEQ, 256>>>(p_h, ln2_w + (size_t)l * HDIM, p_norm);

        gemm_bf16x2_kernel<<<dim3(GUN / 128, SEQ / 128), 256>>>(
            p_norm, p_wgu + (size_t)l * HDIM * GUN, nullptr, p_gu, SEQ, GUN, HDIM);

        silu_mul_kernel<<<(SEQ * IDIM) / 256, 256>>>(p_gu, p_act, SEQ * IDIM);

        gemm_bf16x2_kernel<<<dim3(HDIM / 128, SEQ / 128), 256>>>(
            p_act, p_wdown + (size_t)l * IDIM * HDIM, p_h, p_h, SEQ, HDIM, IDIM);
    }

    rmsnorm_kernel<<<SEQ, 256>>>(p_h, norm_w, p_norm);
    gemm_bf16x2_kernel<<<dim3(VOCAB / 128, SEQ / 128), 256>>>(
        p_norm, p_wlm, nullptr, logits, SEQ, VOCAB, HDIM);
}

// round 13
// speedup vs baseline: 1.9032x; 1.2297x over previous
#include <cuda_runtime.h>
#include <cuda_bf16.h>
#include <stdint.h>
#include <math.h>

#define SEQ 2048
#define HDIM 1024
#define NLAYER 4
#define NH 16
#define NKV 4
#define HD 64
#define IDIM 4096
#define VOCAB 32000
#define QKVN 1536
#define GUN 8192

// ---------------- scratch ----------------
__device__ float g_h[SEQ * HDIM];
__device__ float g_norm[SEQ * HDIM];
__device__ float g_qkv[SEQ * QKVN];
__device__ float g_att[SEQ * NH * HD];
__device__ float g_gu[SEQ * GUN];
__device__ float g_act[SEQ * IDIM];

// activation fragment image (legacy mma layout), max 2048 x 4096
__device__ uint32_t g_aimg[SEQ * IDIM];

// weight images (fragment-slot bf16 hi/lo, 1 uint32/elem)
__device__ uint32_t wp_qkv[NLAYER * HDIM * QKVN];
__device__ uint32_t wp_o[NLAYER * HDIM * HDIM];
__device__ uint32_t wp_gu[NLAYER * HDIM * GUN];
__device__ uint32_t wp_down[NLAYER * IDIM * HDIM];
__device__ uint32_t wp_lm[HDIM * VOCAB];

// pre-split attention operands (per current layer)
__device__ uint32_t g_ks[NKV * SEQ * 64];
__device__ uint32_t g_vthi[NKV * 64 * (SEQ / 2)];
__device__ uint32_t g_vtlo[NKV * 64 * (SEQ / 2)];

// ---------------- helpers ----------------
__device__ __forceinline__ void split2(float x, float y, uint32_t& hi, uint32_t& lo) {
    __nv_bfloat162 h = __floats2bfloat162_rn(x, y);
    hi = *(uint32_t*)&h;
    __nv_bfloat162 l = __floats2bfloat162_rn(x - __bfloat162float(h.x),
                                             y - __bfloat162float(h.y));
    lo = *(uint32_t*)&l;
}

__device__ __forceinline__ void mma_bf16(float* c, const uint32_t* a, const uint32_t* b) {
    asm volatile(
        "mma.sync.aligned.m16n8k16.row.col.f32.bf16.bf16.f32 "
        "{%0,%1,%2,%3}, {%4,%5,%6,%7}, {%8,%9}, {%0,%1,%2,%3};"
        : "+f"(c[0]), "+f"(c[1]), "+f"(c[2]), "+f"(c[3])
        : "r"(a[0]), "r"(a[1]), "r"(a[2]), "r"(a[3]), "r"(b[0]), "r"(b[1]));
}

__device__ __forceinline__ void cp_async16(void* smem, const void* gmem) {
    uint32_t s = (uint32_t)__cvta_generic_to_shared(smem);
    asm volatile("cp.async.cg.shared.global [%0], [%1], 16;" :: "r"(s), "l"(gmem));
}
#define CP_COMMIT() asm volatile("cp.async.commit_group;")
#define CP_WAIT0()  asm volatile("cp.async.wait_group 0;")

// ---------------- weight prep: [K][N] f32 -> fragment-ordered bf16 hi/lo ----------------
__global__ void prep_w_kernel(const float* __restrict__ s0, int st0,
                              const float* __restrict__ s1, int st1,
                              const float* __restrict__ s2, int st2,
                              int n1, int n2, uint32_t* __restrict__ out) {
    int kt = blockIdx.y, nt = blockIdx.x, NT = gridDim.x;
    int t = threadIdx.x;
#pragma unroll
    for (int it = 0; it < 4; it++) {
        int slot = it * 256 + t;
        int lane = slot & 31, in = (slot >> 5) & 15, ik = slot >> 9;
        int g = lane >> 2, c = lane & 3;
        int n = nt * 128 + in * 8 + g;
        int kb = kt * 32 + ik * 16 + 2 * c;
        const float* src; int nn; int st;
        if (n >= n2)      { src = s2; nn = n - n2; st = st2; }
        else if (n >= n1) { src = s1; nn = n - n1; st = st1; }
        else              { src = s0; nn = n;      st = st0; }
        float x0 = src[(size_t)(kb + 0) * st + nn];
        float x1 = src[(size_t)(kb + 1) * st + nn];
        float x8 = src[(size_t)(kb + 8) * st + nn];
        float x9 = src[(size_t)(kb + 9) * st + nn];
        uint4 o;
        uint32_t l01, l89;
        split2(x0, x1, o.x, l01);
        split2(x8, x9, o.y, l89);
        o.z = l01; o.w = l89;
        *(uint4*)&out[((size_t)((size_t)kt * NT + nt) * 1024 + slot) * 4] = o;
    }
}

// ---------------- activation split: [M][K] f32 -> A fragment image ----------------
// chunk (mt, kc): 4096 uint32; index = v*256 + hl*128 + lane*4 + reg
// with v=ik*8+im, row=im*16+((reg&1)<<3)+(lane>>2), kk=ik*16+((reg>>1)<<3)+((lane&3)<<1).
__global__ void split_act_kernel(const float* __restrict__ A, uint32_t* __restrict__ out, int K) {
    int kc = blockIdx.x, mt = blockIdx.y, KT = gridDim.x;
    int tid = threadIdx.x;
    size_t tb = ((size_t)mt * KT + kc) * 4096;
#pragma unroll
    for (int i = 0; i < 8; i++) {
        int j = tid + i * 256;                 // 0..2047 hi-slots
        int reg = j & 3, lane = (j >> 2) & 31, v = j >> 7;
        int im = v & 7, ik = v >> 3;
        int row = im * 16 + ((reg & 1) << 3) + (lane >> 2);
        int kk = ik * 16 + ((reg >> 1) << 3) + ((lane & 3) << 1);
        float2 xy = *(const float2*)(A + (size_t)(mt * 128 + row) * K + kc * 32 + kk);
        uint32_t hi, lo;
        split2(xy.x, xy.y, hi, lo);
        out[tb + v * 256 + lane * 4 + reg] = hi;
        out[tb + v * 256 + 128 + lane * 4 + reg] = lo;
    }
}

// ---------------- bf16x2 (3-term) tensor-core GEMM, all-cp.async mainloop ----------------
__global__ __launch_bounds__(256) void gemm_bf16x2_kernel(
    const uint32_t* __restrict__ Aimg, const uint32_t* __restrict__ Bp,
    const float* __restrict__ Res, float* __restrict__ C,
    int M, int N, int K) {
    __shared__ uint32_t Asm[2][4096];
    __shared__ uint32_t Bsm[2][4096];

    int tid = threadIdx.x, lane = tid & 31, warp = tid >> 5;
    int wm = warp >> 2, wn = warp & 3;
    int bnx = blockIdx.x, mt = blockIdx.y;
    int NT = N >> 7, KT = K >> 5;

    float acc[4][4][4];
#pragma unroll
    for (int im = 0; im < 4; im++)
#pragma unroll
        for (int in = 0; in < 4; in++)
#pragma unroll
            for (int r = 0; r < 4; r++) acc[im][in][r] = 0.f;

#define CPAB(kt, st)                                                                 \
    {                                                                                \
        const uint32_t* aS = Aimg + ((size_t)mt * KT + (kt)) * 4096;                 \
        const uint32_t* bS = Bp + ((size_t)(kt) * NT + bnx) * 4096;                  \
        _Pragma("unroll")                                                            \
        for (int i = 0; i < 4; i++) {                                                \
            int s4 = tid + i * 256;                                                  \
            cp_async16(&Asm[st][s4 * 4], aS + s4 * 4);                               \
            cp_async16(&Bsm[st][s4 * 4], bS + s4 * 4);                               \
        }                                                                            \
    }

#define COMPUTE(st)                                                                  \
    {                                                                                \
        _Pragma("unroll")                                                            \
        for (int ik = 0; ik < 2; ik++) {                                             \
            uint32_t ah[4][4], al[4][4], bh[4][2], bl[4][2];                         \
            _Pragma("unroll")                                                        \
            for (int im = 0; im < 4; im++) {                                         \
                *(uint4*)ah[im] = *(const uint4*)&Asm[st][(((ik * 8 + wm * 4 + im) * 2 + 0) * 32 + lane) * 4]; \
                *(uint4*)al[im] = *(const uint4*)&Asm[st][(((ik * 8 + wm * 4 + im) * 2 + 1) * 32 + lane) * 4]; \
            }                                                                        \
            _Pragma("unroll")                                                        \
            for (int in = 0; in < 4; in++) {                                         \
                uint4 qv = *(const uint4*)&Bsm[st][((ik * 16 + wn * 4 + in) * 32 + lane) * 4]; \
                bh[in][0] = qv.x; bh[in][1] = qv.y;                                  \
                bl[in][0] = qv.z; bl[in][1] = qv.w;                                  \
            }                                                                        \
            _Pragma("unroll")                                                        \
            for (int im = 0; im < 4; im++)                                           \
                _Pragma("unroll")                                                    \
                for (int in = 0; in < 4; in++) {                                     \
                    mma_bf16(acc[im][in], ah[im], bl[in]);                           \
                    mma_bf16(acc[im][in], al[im], bh[in]);                           \
                    mma_bf16(acc[im][in], ah[im], bh[in]);                           \
                }                                                                    \
        }                                                                            \
    }

    CPAB(0, 0); CP_COMMIT();
    CP_WAIT0();
    __syncthreads();

    for (int kt = 0; kt < KT; kt++) {
        int st = kt & 1;
        if (kt + 1 < KT) { CPAB(kt + 1, st ^ 1); CP_COMMIT(); }
        COMPUTE(st);
        if (kt + 1 < KT) { CP_WAIT0(); }
        __syncthreads();
    }

    int gid = lane >> 2, tig = lane & 3;
#pragma unroll
    for (int im = 0; im < 4; im++) {
#pragma unroll
        for (int in = 0; in < 4; in++) {
            int row0 = mt * 128 + wm * 64 + im * 16 + gid;
            int col = bnx * 128 + wn * 32 + in * 8 + tig * 2;
            float2 v0 = make_float2(acc[im][in][0], acc[im][in][1]);
            float2 v1 = make_float2(acc[im][in][2], acc[im][in][3]);
            if (Res) {
                float2 r0 = *(const float2*)(Res + (size_t)row0 * N + col);
                float2 r1 = *(const float2*)(Res + (size_t)(row0 + 8) * N + col);
                v0.x += r0.x; v0.y += r0.y;
                v1.x += r1.x; v1.y += r1.y;
            }
            *(float2*)(C + (size_t)row0 * N + col) = v0;
            *(float2*)(C + (size_t)(row0 + 8) * N + col) = v1;
        }
    }
#undef CPAB
#undef COMPUTE
}

// ---------------- embedding + audio scatter ----------------
__global__ void embed_scatter_kernel(const int* __restrict__ ids,
                                     const float* __restrict__ emb,
                                     const float* __restrict__ audio,
                                     const int* __restrict__ aoff,
                                     float* __restrict__ h) {
    int s = blockIdx.x;
    int off = aoff[0];
    const float* src;
    if (s >= off && s < off + 256) src = audio + (size_t)(s - off) * HDIM;
    else                           src = emb + (size_t)ids[s] * HDIM;
    float* dst = h + (size_t)s * HDIM;
    int i = threadIdx.x * 4;
    *(float4*)&dst[i] = *(const float4*)&src[i];
}

// ---------------- RMSNorm H=1024 ----------------
__global__ void rmsnorm_kernel(const float* __restrict__ x,
                               const float* __restrict__ w,
                               float* __restrict__ out) {
    int s = blockIdx.x;
    const float* xr = x + (size_t)s * HDIM;
    float ss = 0.f;
#pragma unroll
    for (int i = 0; i < 4; i++) { float v = xr[threadIdx.x + i * 256]; ss += v * v; }
    __shared__ float red[8];
#pragma unroll
    for (int o = 16; o; o >>= 1) ss += __shfl_xor_sync(0xffffffffu, ss, o);
    if ((threadIdx.x & 31) == 0) red[threadIdx.x >> 5] = ss;
    __syncthreads();
    if (threadIdx.x < 32) {
        float v = (threadIdx.x < 8) ? red[threadIdx.x] : 0.f;
#pragma unroll
        for (int o = 4; o; o >>= 1) v += __shfl_xor_sync(0xffffffffu, v, o);
        if (threadIdx.x == 0) red[0] = v;
    }
    __syncthreads();
    float r = rsqrtf(red[0] * (1.f / HDIM) + 1e-6f);
    float* orow = out + (size_t)s * HDIM;
#pragma unroll
    for (int i = 0; i < 4; i++) { int id = threadIdx.x + i * 256; orow[id] = xr[id] * r * w[id]; }
}

// ---------------- per-head RMSNorm + RoPE ----------------
__global__ void rms_rope_kernel(const float* __restrict__ in, int stride,
                                const float* __restrict__ w,
                                const int* __restrict__ pos_ids,
                                float* __restrict__ out_nat,
                                float* __restrict__ present,
                                int nh) {
    int s = blockIdx.x;
    int warp = threadIdx.x >> 5, lane = threadIdx.x & 31;
    int h = blockIdx.y * 4 + warp;
    if (h >= nh) return;
    const float* x = in + (size_t)s * stride + h * HD;
    float x0 = x[lane], x1 = x[lane + 32];
    float ss = x0 * x0 + x1 * x1;
#pragma unroll
    for (int o = 16; o; o >>= 1) ss += __shfl_xor_sync(0xffffffffu, ss, o);
    float r = rsqrtf(ss * (1.f / HD) + 1e-6f);
    x0 = x0 * r * w[lane];
    x1 = x1 * r * w[lane + 32];
    float pos = (float)pos_ids[s];
    float invf = expf(-((float)lane * (1.f / 32.f)) * 9.210340371976184f);
    float ang = pos * invf;
    float c, sn;
    sincosf(ang, &sn, &c);
    float o0 = x0 * c - x1 * sn;
    float o1 = x1 * c + x0 * sn;
    if (out_nat) {
        float* op = out_nat + (size_t)s * stride + h * HD;
        op[lane] = o0; op[lane + 32] = o1;
    }
    if (present) {
        float* pp = present + ((size_t)h * SEQ + s) * HD;
        pp[lane] = o0; pp[lane + 32] = o1;
    }
}

// ---------------- copy V into present_values [NKV,S,HD] ----------------
__global__ void copy_v_kernel(const float* __restrict__ qkv, float* __restrict__ pv) {
    int s = blockIdx.x;
    int t = threadIdx.x;
    int kv = t >> 6, d = t & 63;
    pv[((size_t)kv * SEQ + s) * HD + d] = qkv[(size_t)s * QKVN + 1280 + t];
}

// ---------------- split K for attention ----------------
__global__ void split_k_kernel(const float* __restrict__ pk, uint32_t* __restrict__ ks) {
    int p = blockIdx.x * 256 + threadIdx.x;
    int row = p >> 5, dg = p & 31;
    float2 v = *(const float2*)&pk[(size_t)row * HD + dg * 2];
    uint32_t hi, lo;
    split2(v.x, v.y, hi, lo);
    ks[(size_t)row * 64 + dg] = hi;
    ks[(size_t)row * 64 + 32 + dg] = lo;
}

// ---------------- split V^T for attention ----------------
__global__ void split_vt_kernel(const float* __restrict__ pv,
                                uint32_t* __restrict__ vthi, uint32_t* __restrict__ vtlo) {
    int p = blockIdx.x * 256 + threadIdx.x;
    int kvh = p >> 16, rem = p & 65535;
    int sp = rem >> 6, d = rem & 63;
    float v0 = pv[((size_t)kvh * SEQ + 2 * sp) * HD + d];
    float v1 = pv[((size_t)kvh * SEQ + 2 * sp + 1) * HD + d];
    uint32_t hi, lo;
    split2(v0, v1, hi, lo);
    vthi[((size_t)kvh * 64 + d) * (SEQ / 2) + sp] = hi;
    vtlo[((size_t)kvh * 64 + d) * (SEQ / 2) + sp] = lo;
}

// ---------------- tensor-core flash attention (128 q-rows/block) ----------------
__global__ __launch_bounds__(256) void attn_mma_kernel(const float* __restrict__ q,
                                                       const uint32_t* __restrict__ Ks,
                                                       const uint32_t* __restrict__ Vthi,
                                                       const uint32_t* __restrict__ Vtlo,
                                                       float* __restrict__ o) {
    __shared__ uint32_t KHi[64 * 36], KLo[64 * 36];
    __shared__ uint32_t VHi[64 * 36], VLo[64 * 36];

    int qb = blockIdx.x, h = blockIdx.y, kvh = h >> 2;
    int tid = threadIdx.x, w = tid >> 5, lane = tid & 31;
    int gid = lane >> 2, tig = lane & 3;

    uint32_t qh[4][4], ql[4][4];
    int rmin = qb * 128 + w * 16;
    {
        const float* q0 = q + (size_t)(rmin + gid) * QKVN + h * HD;
        const float* q1 = q0 + 8 * QKVN;
#pragma unroll
        for (int c = 0; c < 4; c++) {
            float2 x0 = *(const float2*)(q0 + c * 16 + tig * 2);
            float2 x1 = *(const float2*)(q1 + c * 16 + tig * 2);
            float2 x2 = *(const float2*)(q0 + c * 16 + 8 + tig * 2);
            float2 x3 = *(const float2*)(q1 + c * 16 + 8 + tig * 2);
            split2(x0.x * 0.125f, x0.y * 0.125f, qh[c][0], ql[c][0]);
            split2(x1.x * 0.125f, x1.y * 0.125f, qh[c][1], ql[c][1]);
            split2(x2.x * 0.125f, x2.y * 0.125f, qh[c][2], ql[c][2]);
            split2(x3.x * 0.125f, x3.y * 0.125f, qh[c][3], ql[c][3]);
        }
    }

    float m0 = -1e30f, m1 = -1e30f, l0 = 0.f, l1 = 0.f;
    float acc[8][4];
#pragma unroll
    for (int nb = 0; nb < 8; nb++)
#pragma unroll
        for (int r = 0; r < 4; r++) acc[nb][r] = 0.f;

    int ktend = 2 * qb + 1;
    for (int kt = 0; kt <= ktend; kt++) {
#pragma unroll
        for (int i = 0; i < 4; i++) {
            int c0 = tid + i * 256;
            int row = c0 >> 4, part = c0 & 15;
            const uint32_t* src = Ks + ((size_t)(kvh * SEQ + kt * 64 + row)) * 64
                                  + ((part >> 3) * 32) + ((part & 7) * 4);
            uint32_t* dst = ((part >> 3) ? KLo : KHi) + row * 36 + (part & 7) * 4;
            cp_async16(dst, src);
        }
#pragma unroll
        for (int i = 0; i < 4; i++) {
            int c0 = tid + i * 256;
            int d = c0 >> 4, part = c0 & 15;
            const uint32_t* src = ((part >> 3) ? Vtlo : Vthi)
                                  + ((size_t)kvh * 64 + d) * (SEQ / 2) + kt * 32 + (part & 7) * 4;
            uint32_t* dst = ((part >> 3) ? VLo : VHi) + d * 36 + (part & 7) * 4;
            cp_async16(dst, src);
        }
        CP_COMMIT();
        CP_WAIT0();
        __syncthreads();

        bool skip = (kt * 64 > rmin + 15);
        if (!skip) {
            float sc[8][4];
#pragma unroll
            for (int nb = 0; nb < 8; nb++)
#pragma unroll
                for (int r = 0; r < 4; r++) sc[nb][r] = 0.f;

#pragma unroll
            for (int c = 0; c < 4; c++) {
#pragma unroll
                for (int nb = 0; nb < 8; nb++) {
                    int srow = (nb * 8 + gid) * 36 + c * 8 + tig;
                    uint32_t bh[2] = {KHi[srow], KHi[srow + 4]};
                    uint32_t bl[2] = {KLo[srow], KLo[srow + 4]};
                    mma_bf16(sc[nb], qh[c], bl);
                    mma_bf16(sc[nb], ql[c], bh);
                    mma_bf16(sc[nb], qh[c], bh);
                }
            }

            if (kt * 64 + 63 > rmin) {
                int r0 = rmin + gid, r1 = rmin + 8 + gid;
#pragma unroll
                for (int nb = 0; nb < 8; nb++) {
#pragma unroll
                    for (int j = 0; j < 2; j++) {
                        int col = kt * 64 + nb * 8 + tig * 2 + j;
                        if (col > r0) sc[nb][j] = -1e30f;
                        if (col > r1) sc[nb][2 + j] = -1e30f;
                    }
                }
            }

            float mx0 = -1e30f, mx1 = -1e30f;
#pragma unroll
            for (int nb = 0; nb < 8; nb++) {
                mx0 = fmaxf(mx0, fmaxf(sc[nb][0], sc[nb][1]));
                mx1 = fmaxf(mx1, fmaxf(sc[nb][2], sc[nb][3]));
            }
            mx0 = fmaxf(mx0, __shfl_xor_sync(0xffffffffu, mx0, 1));
            mx0 = fmaxf(mx0, __shfl_xor_sync(0xffffffffu, mx0, 2));
            mx1 = fmaxf(mx1, __shfl_xor_sync(0xffffffffu, mx1, 1));
            mx1 = fmaxf(mx1, __shfl_xor_sync(0xffffffffu, mx1, 2));
            float mn0 = fmaxf(m0, mx0), mn1 = fmaxf(m1, mx1);
            float al0 = __expf(m0 - mn0), al1 = __expf(m1 - mn1);
            float s0 = 0.f, s1 = 0.f;
#pragma unroll
            for (int nb = 0; nb < 8; nb++) {
                sc[nb][0] = __expf(sc[nb][0] - mn0);
                sc[nb][1] = __expf(sc[nb][1] - mn0);
                sc[nb][2] = __expf(sc[nb][2] - mn1);
                sc[nb][3] = __expf(sc[nb][3] - mn1);
                s0 += sc[nb][0] + sc[nb][1];
                s1 += sc[nb][2] + sc[nb][3];
            }
            s0 += __shfl_xor_sync(0xffffffffu, s0, 1);
            s0 += __shfl_xor_sync(0xffffffffu, s0, 2);
            s1 += __shfl_xor_sync(0xffffffffu, s1, 1);
            s1 += __shfl_xor_sync(0xffffffffu, s1, 2);
            l0 = l0 * al0 + s0; m0 = mn0;
            l1 = l1 * al1 + s1; m1 = mn1;
#pragma unroll
            for (int nb = 0; nb < 8; nb++) {
                acc[nb][0] *= al0; acc[nb][1] *= al0;
                acc[nb][2] *= al1; acc[nb][3] *= al1;
            }

#pragma unroll
            for (int c = 0; c < 4; c++) {
                uint32_t ah[4], al_[4];
                split2(sc[2 * c][0],     sc[2 * c][1],     ah[0], al_[0]);
                split2(sc[2 * c][2],     sc[2 * c][3],     ah[1], al_[1]);
                split2(sc[2 * c + 1][0], sc[2 * c + 1][1], ah[2], al_[2]);
                split2(sc[2 * c + 1][2], sc[2 * c + 1][3], ah[3], al_[3]);
#pragma unroll
                for (int nb = 0; nb < 8; nb++) {
                    int drow = (nb * 8 + gid) * 36 + c * 8 + tig;
                    uint32_t bh[2] = {VHi[drow], VHi[drow + 4]};
                    uint32_t bl[2] = {VLo[drow], VLo[drow + 4]};
                    mma_bf16(acc[nb], ah, bl);
                    mma_bf16(acc[nb], al_, bh);
                    mma_bf16(acc[nb], ah, bh);
                }
            }
        }
        __syncthreads();
    }

    float inv0 = 1.f / l0, inv1 = 1.f / l1;
    int row0 = rmin + gid;
#pragma unroll
    for (int nb = 0; nb < 8; nb++) {
        int col = h * HD + nb * 8 + tig * 2;
        *(float2*)&o[(size_t)row0 * (NH * HD) + col] =
            make_float2(acc[nb][0] * inv0, acc[nb][1] * inv0);
        *(float2*)&o[(size_t)(row0 + 8) * (NH * HD) + col] =
            make_float2(acc[nb][2] * inv1, acc[nb][3] * inv1);
    }
}

// ---------------- silu(g) * u ----------------
__global__ void silu_mul_kernel(const float* __restrict__ gu, float* __restrict__ out, int n) {
    int i = blockIdx.x * 256 + threadIdx.x;
    if (i < n) {
        int s = i >> 12, c = i & 4095;
        float x = gu[(size_t)s * GUN + c];
        float u = gu[(size_t)s * GUN + IDIM + c];
        out[i] = x / (1.f + __expf(-x)) * u;
    }
}

// ---------------- host launch ----------------
extern "C" void kernel_launch(void* const* d_in, const int* in_sizes, int n_in,
                              void* d_out, int out_size) {
    (void)in_sizes; (void)n_in; (void)out_size;

    static bool init = false;
    static float *p_h, *p_norm, *p_qkv, *p_att, *p_gu, *p_act;
    static uint32_t *p_wqkv, *p_wo, *p_wgu, *p_wdown, *p_wlm;
    static uint32_t *p_ks, *p_vthi, *p_vtlo, *p_aimg;
    if (!init) {
        cudaGetSymbolAddress((void**)&p_h, g_h);
        cudaGetSymbolAddress((void**)&p_norm, g_norm);
        cudaGetSymbolAddress((void**)&p_qkv, g_qkv);
        cudaGetSymbolAddress((void**)&p_att, g_att);
        cudaGetSymbolAddress((void**)&p_gu, g_gu);
        cudaGetSymbolAddress((void**)&p_act, g_act);
        cudaGetSymbolAddress((void**)&p_wqkv, wp_qkv);
        cudaGetSymbolAddress((void**)&p_wo, wp_o);
        cudaGetSymbolAddress((void**)&p_wgu, wp_gu);
        cudaGetSymbolAddress((void**)&p_wdown, wp_down);
        cudaGetSymbolAddress((void**)&p_wlm, wp_lm);
        cudaGetSymbolAddress((void**)&p_ks, g_ks);
        cudaGetSymbolAddress((void**)&p_vthi, g_vthi);
        cudaGetSymbolAddress((void**)&p_vtlo, g_vtlo);
        cudaGetSymbolAddress((void**)&p_aimg, g_aimg);
        init = true;
    }

    const int*   ids    = (const int*)d_in[0];
    const int*   pos    = (const int*)d_in[1];
    const float* audio  = (const float*)d_in[2];
    const int*   aoff   = (const int*)d_in[3];
    const float* embw   = (const float*)d_in[4];
    const float* q_w    = (const float*)d_in[5];
    const float* k_w    = (const float*)d_in[6];
    const float* v_w    = (const float*)d_in[7];
    const float* o_w    = (const float*)d_in[8];
    const float* qn_w   = (const float*)d_in[9];
    const float* kn_w   = (const float*)d_in[10];
    const float* ln1_w  = (const float*)d_in[11];
    const float* ln2_w  = (const float*)d_in[12];
    const float* gate_w = (const float*)d_in[13];
    const float* up_w   = (const float*)d_in[14];
    const float* down_w = (const float*)d_in[15];
    const float* norm_w = (const float*)d_in[16];
    const float* lm_w   = (const float*)d_in[17];

    float* out    = (float*)d_out;
    float* logits = out;
    float* pk     = out + (size_t)SEQ * VOCAB;
    float* pv     = pk + (size_t)NLAYER * NKV * SEQ * HD;

    const int BIG = 1 << 30;

    for (int l = 0; l < NLAYER; l++) {
        prep_w_kernel<<<dim3(QKVN / 128, HDIM / 32), 256>>>(
            q_w + (size_t)l * HDIM * (NH * HD), NH * HD,
            k_w + (size_t)l * HDIM * (NKV * HD), NKV * HD,
            v_w + (size_t)l * HDIM * (NKV * HD), NKV * HD,
            NH * HD, NH * HD + NKV * HD,
            p_wqkv + (size_t)l * HDIM * QKVN);
        prep_w_kernel<<<dim3(HDIM / 128, HDIM / 32), 256>>>(
            o_w + (size_t)l * HDIM * HDIM, HDIM, o_w, HDIM, o_w, HDIM, BIG, BIG,
            p_wo + (size_t)l * HDIM * HDIM);
        prep_w_kernel<<<dim3(GUN / 128, HDIM / 32), 256>>>(
            gate_w + (size_t)l * HDIM * IDIM, IDIM,
            up_w + (size_t)l * HDIM * IDIM, IDIM,
            up_w, IDIM, IDIM, BIG,
            p_wgu + (size_t)l * HDIM * GUN);
        prep_w_kernel<<<dim3(HDIM / 128, IDIM / 32), 256>>>(
            down_w + (size_t)l * IDIM * HDIM, HDIM, down_w, HDIM, down_w, HDIM, BIG, BIG,
            p_wdown + (size_t)l * IDIM * HDIM);
    }
    prep_w_kernel<<<dim3(VOCAB / 128, HDIM / 32), 256>>>(
        lm_w, VOCAB, lm_w, VOCAB, lm_w, VOCAB, BIG, BIG, p_wlm);

    embed_scatter_kernel<<<SEQ, 256>>>(ids, embw, audio, aoff, p_h);

    for (int l = 0; l < NLAYER; l++) {
        float* pk_l = pk + (size_t)l * NKV * SEQ * HD;
        float* pv_l = pv + (size_t)l * NKV * SEQ * HD;

        rmsnorm_kernel<<<SEQ, 256>>>(p_h, ln1_w + (size_t)l * HDIM, p_norm);

        split_act_kernel<<<dim3(HDIM / 32, SEQ / 128), 256>>>(p_norm, p_aimg, HDIM);
        gemm_bf16x2_kernel<<<dim3(QKVN / 128, SEQ / 128), 256>>>(
            p_aimg, p_wqkv + (size_t)l * HDIM * QKVN, nullptr, p_qkv, SEQ, QKVN, HDIM);

        rms_rope_kernel<<<dim3(SEQ, 4), 128>>>(p_qkv, QKVN, qn_w + (size_t)l * HD, pos,
                                               p_qkv, nullptr, NH);
        rms_rope_kernel<<<dim3(SEQ, 1), 128>>>(p_qkv + NH * HD, QKVN, kn_w + (size_t)l * HD, pos,
                                               nullptr, pk_l, NKV);
        copy_v_kernel<<<SEQ, 256>>>(p_qkv, pv_l);

        split_k_kernel<<<NKV * SEQ * 32 / 256, 256>>>(pk_l, p_ks);
        split_vt_kernel<<<NKV * 64 * (SEQ / 2) / 256, 256>>>(pv_l, p_vthi, p_vtlo);

        attn_mma_kernel<<<dim3(SEQ / 128, NH), 256>>>(p_qkv, p_ks, p_vthi, p_vtlo, p_att);

        split_act_kernel<<<dim3(HDIM / 32, SEQ / 128), 256>>>(p_att, p_aimg, HDIM);
        gemm_bf16x2_kernel<<<dim3(HDIM / 128, SEQ / 128), 256>>>(
            p_aimg, p_wo + (size_t)l * HDIM * HDIM, p_h, p_h, SEQ, HDIM, HDIM);

        rmsnorm_kernel<<<SEQ, 256>>>(p_h, ln2_w + (size_t)l * HDIM, p_norm);

        split_act_kernel<<<dim3(HDIM / 32, SEQ / 128), 256>>>(p_norm, p_aimg, HDIM);
        gemm_bf16x2_kernel<<<dim3(GUN / 128, SEQ / 128), 256>>>(
            p_aimg, p_wgu + (size_t)l * HDIM * GUN, nullptr, p_gu, SEQ, GUN, HDIM);

        silu_mul_kernel<<<(SEQ * IDIM) / 256, 256>>>(p_gu, p_act, SEQ * IDIM);

        split_act_kernel<<<dim3(IDIM / 32, SEQ / 128), 256>>>(p_act, p_aimg, IDIM);
        gemm_bf16x2_kernel<<<dim3(HDIM / 128, SEQ / 128), 256>>>(
            p_aimg, p_wdown + (size_t)l * IDIM * HDIM, p_h, p_h, SEQ, HDIM, IDIM);
    }

    rmsnorm_kernel<<<SEQ, 256>>>(p_h, norm_w, p_norm);
    split_act_kernel<<<dim3(HDIM / 32, SEQ / 128), 256>>>(p_norm, p_aimg, HDIM);
    gemm_bf16x2_kernel<<<dim3(VOCAB / 128, SEQ / 128), 256>>>(
        p_aimg, p_wlm, nullptr, logits, SEQ, VOCAB, HDIM);
}

// round 15
// speedup vs baseline: 1.9441x; 1.0215x over previous
#include <cuda_runtime.h>
#include <cuda_bf16.h>
#include <stdint.h>
#include <math.h>

#define SEQ 2048
#define HDIM 1024
#define NLAYER 4
#define NH 16
#define NKV 4
#define HD 64
#define IDIM 4096
#define VOCAB 32000
#define QKVN 1536
#define GUN 8192

// ---------------- scratch ----------------
__device__ float g_h[SEQ * HDIM];
__device__ float g_qkv[SEQ * QKVN];
__device__ float g_gu[SEQ * GUN];

// activation fragment image (legacy mma layout), max 2048 x 4096
__device__ uint32_t g_aimg[SEQ * IDIM];

// weight images (fragment-slot bf16 hi/lo, 1 uint32/elem)
__device__ uint32_t wp_qkv[NLAYER * HDIM * QKVN];
__device__ uint32_t wp_o[NLAYER * HDIM * HDIM];
__device__ uint32_t wp_gu[NLAYER * HDIM * GUN];
__device__ uint32_t wp_down[NLAYER * IDIM * HDIM];
__device__ uint32_t wp_lm[HDIM * VOCAB];

// pre-split attention operands (per current layer)
__device__ uint32_t g_ks[NKV * SEQ * 64];
__device__ uint32_t g_vthi[NKV * 64 * (SEQ / 2)];
__device__ uint32_t g_vtlo[NKV * 64 * (SEQ / 2)];

// ---------------- helpers ----------------
__device__ __forceinline__ void split2(float x, float y, uint32_t& hi, uint32_t& lo) {
    __nv_bfloat162 h = __floats2bfloat162_rn(x, y);
    hi = *(uint32_t*)&h;
    __nv_bfloat162 l = __floats2bfloat162_rn(x - __bfloat162float(h.x),
                                             y - __bfloat162float(h.y));
    lo = *(uint32_t*)&l;
}

// write one (row, k..k+1) fp32 pair into the A fragment image (k even)
__device__ __forceinline__ void store_frag(uint32_t* __restrict__ img, int KT,
                                           int row, int k, float x, float y) {
    int mt = row >> 7, rl = row & 127;
    int kc = k >> 5, kl = k & 31;
    int lane = ((rl & 7) << 2) | ((kl >> 1) & 3);
    int reg = (((kl >> 3) & 1) << 1) | ((rl >> 3) & 1);
    int v = ((kl >> 4) << 3) | (rl >> 4);
    size_t base = ((size_t)mt * KT + kc) * 4096 + v * 256 + lane * 4 + reg;
    uint32_t hi, lo;
    split2(x, y, hi, lo);
    img[base] = hi;
    img[base + 128] = lo;
}

__device__ __forceinline__ void mma_bf16(float* c, const uint32_t* a, const uint32_t* b) {
    asm volatile(
        "mma.sync.aligned.m16n8k16.row.col.f32.bf16.bf16.f32 "
        "{%0,%1,%2,%3}, {%4,%5,%6,%7}, {%8,%9}, {%0,%1,%2,%3};"
        : "+f"(c[0]), "+f"(c[1]), "+f"(c[2]), "+f"(c[3])
        : "r"(a[0]), "r"(a[1]), "r"(a[2]), "r"(a[3]), "r"(b[0]), "r"(b[1]));
}

__device__ __forceinline__ void cp_async16(void* smem, const void* gmem) {
    uint32_t s = (uint32_t)__cvta_generic_to_shared(smem);
    asm volatile("cp.async.cg.shared.global [%0], [%1], 16;" :: "r"(s), "l"(gmem));
}
#define CP_COMMIT() asm volatile("cp.async.commit_group;")
#define CP_WAIT0()  asm volatile("cp.async.wait_group 0;")

// ---------------- weight prep: [K][N] f32 -> fragment-ordered bf16 hi/lo ----------------
__global__ void prep_w_kernel(const float* __restrict__ s0, int st0,
                              const float* __restrict__ s1, int st1,
                              const float* __restrict__ s2, int st2,
                              int n1, int n2, uint32_t* __restrict__ out) {
    int kt = blockIdx.y, nt = blockIdx.x, NT = gridDim.x;
    int t = threadIdx.x;
#pragma unroll
    for (int it = 0; it < 4; it++) {
        int slot = it * 256 + t;
        int lane = slot & 31, in = (slot >> 5) & 15, ik = slot >> 9;
        int g = lane >> 2, c = lane & 3;
        int n = nt * 128 + in * 8 + g;
        int kb = kt * 32 + ik * 16 + 2 * c;
        const float* src; int nn; int st;
        if (n >= n2)      { src = s2; nn = n - n2; st = st2; }
        else if (n >= n1) { src = s1; nn = n - n1; st = st1; }
        else              { src = s0; nn = n;      st = st0; }
        float x0 = src[(size_t)(kb + 0) * st + nn];
        float x1 = src[(size_t)(kb + 1) * st + nn];
        float x8 = src[(size_t)(kb + 8) * st + nn];
        float x9 = src[(size_t)(kb + 9) * st + nn];
        uint4 o;
        uint32_t l01, l89;
        split2(x0, x1, o.x, l01);
        split2(x8, x9, o.y, l89);
        o.z = l01; o.w = l89;
        *(uint4*)&out[((size_t)((size_t)kt * NT + nt) * 1024 + slot) * 4] = o;
    }
}

// ---------------- bf16x2 (3-term) tensor-core GEMM, all-cp.async mainloop ----------------
__global__ __launch_bounds__(256) void gemm_bf16x2_kernel(
    const uint32_t* __restrict__ Aimg, const uint32_t* __restrict__ Bp,
    const float* __restrict__ Res, float* __restrict__ C,
    int M, int N, int K) {
    __shared__ uint32_t Asm[2][4096];
    __shared__ uint32_t Bsm[2][4096];

    int tid = threadIdx.x, lane = tid & 31, warp = tid >> 5;
    int wm = warp >> 2, wn = warp & 3;
    int bnx = blockIdx.x, mt = blockIdx.y;
    int NT = N >> 7, KT = K >> 5;

    float acc[4][4][4];
#pragma unroll
    for (int im = 0; im < 4; im++)
#pragma unroll
        for (int in = 0; in < 4; in++)
#pragma unroll
            for (int r = 0; r < 4; r++) acc[im][in][r] = 0.f;

#define CPAB(kt, st)                                                                 \
    {                                                                                \
        const uint32_t* aS = Aimg + ((size_t)mt * KT + (kt)) * 4096;                 \
        const uint32_t* bS = Bp + ((size_t)(kt) * NT + bnx) * 4096;                  \
        _Pragma("unroll")                                                            \
        for (int i = 0; i < 4; i++) {                                                \
            int s4 = tid + i * 256;                                                  \
            cp_async16(&Asm[st][s4 * 4], aS + s4 * 4);                               \
            cp_async16(&Bsm[st][s4 * 4], bS + s4 * 4);                               \
        }                                                                            \
    }

#define COMPUTE(st)                                                                  \
    {                                                                                \
        _Pragma("unroll")                                                            \
        for (int ik = 0; ik < 2; ik++) {                                             \
            uint32_t ah[4][4], al[4][4], bh[4][2], bl[4][2];                         \
            _Pragma("unroll")                                                        \
            for (int im = 0; im < 4; im++) {                                         \
                *(uint4*)ah[im] = *(const uint4*)&Asm[st][(((ik * 8 + wm * 4 + im) * 2 + 0) * 32 + lane) * 4]; \
                *(uint4*)al[im] = *(const uint4*)&Asm[st][(((ik * 8 + wm * 4 + im) * 2 + 1) * 32 + lane) * 4]; \
            }                                                                        \
            _Pragma("unroll")                                                        \
            for (int in = 0; in < 4; in++) {                                         \
                uint4 qv = *(const uint4*)&Bsm[st][((ik * 16 + wn * 4 + in) * 32 + lane) * 4]; \
                bh[in][0] = qv.x; bh[in][1] = qv.y;                                  \
                bl[in][0] = qv.z; bl[in][1] = qv.w;                                  \
            }                                                                        \
            _Pragma("unroll")                                                        \
            for (int im = 0; im < 4; im++)                                           \
                _Pragma("unroll")                                                    \
                for (int in = 0; in < 4; in++) {                                     \
                    mma_bf16(acc[im][in], ah[im], bl[in]);                           \
                    mma_bf16(acc[im][in], al[im], bh[in]);                           \
                    mma_bf16(acc[im][in], ah[im], bh[in]);                           \
                }                                                                    \
        }                                                                            \
    }

    CPAB(0, 0); CP_COMMIT();
    CP_WAIT0();
    __syncthreads();

    for (int kt = 0; kt < KT; kt++) {
        int st = kt & 1;
        if (kt + 1 < KT) { CPAB(kt + 1, st ^ 1); CP_COMMIT(); }
        COMPUTE(st);
        if (kt + 1 < KT) { CP_WAIT0(); }
        __syncthreads();
    }

    int gid = lane >> 2, tig = lane & 3;
#pragma unroll
    for (int im = 0; im < 4; im++) {
#pragma unroll
        for (int in = 0; in < 4; in++) {
            int row0 = mt * 128 + wm * 64 + im * 16 + gid;
            int col = bnx * 128 + wn * 32 + in * 8 + tig * 2;
            float2 v0 = make_float2(acc[im][in][0], acc[im][in][1]);
            float2 v1 = make_float2(acc[im][in][2], acc[im][in][3]);
            if (Res) {
                float2 r0 = *(const float2*)(Res + (size_t)row0 * N + col);
                float2 r1 = *(const float2*)(Res + (size_t)(row0 + 8) * N + col);
                v0.x += r0.x; v0.y += r0.y;
                v1.x += r1.x; v1.y += r1.y;
            }
            *(float2*)(C + (size_t)row0 * N + col) = v0;
            *(float2*)(C + (size_t)(row0 + 8) * N + col) = v1;
        }
    }
#undef CPAB
#undef COMPUTE
}

// ---------------- embedding + audio scatter ----------------
__global__ void embed_scatter_kernel(const int* __restrict__ ids,
                                     const float* __restrict__ emb,
                                     const float* __restrict__ audio,
                                     const int* __restrict__ aoff,
                                     float* __restrict__ h) {
    int s = blockIdx.x;
    int off = aoff[0];
    const float* src;
    if (s >= off && s < off + 256) src = audio + (size_t)(s - off) * HDIM;
    else                           src = emb + (size_t)ids[s] * HDIM;
    float* dst = h + (size_t)s * HDIM;
    int i = threadIdx.x * 4;
    *(float4*)&dst[i] = *(const float4*)&src[i];
}

// ---------------- RMSNorm H=1024 -> fragment image ----------------
__global__ void rmsnorm_frag_kernel(const float* __restrict__ x,
                                    const float* __restrict__ w,
                                    uint32_t* __restrict__ img) {
    int s = blockIdx.x;
    const float* xr = x + (size_t)s * HDIM;
    float ss = 0.f;
#pragma unroll
    for (int i = 0; i < 4; i++) { float v = xr[threadIdx.x + i * 256]; ss += v * v; }
    __shared__ float red[8];
#pragma unroll
    for (int o = 16; o; o >>= 1) ss += __shfl_xor_sync(0xffffffffu, ss, o);
    if ((threadIdx.x & 31) == 0) red[threadIdx.x >> 5] = ss;
    __syncthreads();
    if (threadIdx.x < 32) {
        float v = (threadIdx.x < 8) ? red[threadIdx.x] : 0.f;
#pragma unroll
        for (int o = 4; o; o >>= 1) v += __shfl_xor_sync(0xffffffffu, v, o);
        if (threadIdx.x == 0) red[0] = v;
    }
    __syncthreads();
    float r = rsqrtf(red[0] * (1.f / HDIM) + 1e-6f);
#pragma unroll
    for (int i = 0; i < 2; i++) {
        int k = 2 * threadIdx.x + i * 512;
        float a = xr[k] * r * w[k];
        float b = xr[k + 1] * r * w[k + 1];
        store_frag(img, HDIM / 32, s, k, a, b);
    }
}

// ---------------- per-head RMSNorm + RoPE ----------------
__global__ void rms_rope_kernel(const float* __restrict__ in, int stride,
                                const float* __restrict__ w,
                                const int* __restrict__ pos_ids,
                                float* __restrict__ out_nat,
                                float* __restrict__ present,
                                int nh) {
    int s = blockIdx.x;
    int warp = threadIdx.x >> 5, lane = threadIdx.x & 31;
    int h = blockIdx.y * 4 + warp;
    if (h >= nh) return;
    const float* x = in + (size_t)s * stride + h * HD;
    float x0 = x[lane], x1 = x[lane + 32];
    float ss = x0 * x0 + x1 * x1;
#pragma unroll
    for (int o = 16; o; o >>= 1) ss += __shfl_xor_sync(0xffffffffu, ss, o);
    float r = rsqrtf(ss * (1.f / HD) + 1e-6f);
    x0 = x0 * r * w[lane];
    x1 = x1 * r * w[lane + 32];
    float pos = (float)pos_ids[s];
    float invf = expf(-((float)lane * (1.f / 32.f)) * 9.210340371976184f);
    float ang = pos * invf;
    float c, sn;
    sincosf(ang, &sn, &c);
    float o0 = x0 * c - x1 * sn;
    float o1 = x1 * c + x0 * sn;
    if (out_nat) {
        float* op = out_nat + (size_t)s * stride + h * HD;
        op[lane] = o0; op[lane + 32] = o1;
    }
    if (present) {
        float* pp = present + ((size_t)h * SEQ + s) * HD;
        pp[lane] = o0; pp[lane + 32] = o1;
    }
}

// ---------------- copy V into present_values [NKV,S,HD] ----------------
__global__ void copy_v_kernel(const float* __restrict__ qkv, float* __restrict__ pv) {
    int s = blockIdx.x;
    int t = threadIdx.x;
    int kv = t >> 6, d = t & 63;
    pv[((size_t)kv * SEQ + s) * HD + d] = qkv[(size_t)s * QKVN + 1280 + t];
}

// ---------------- split K for attention ----------------
__global__ void split_k_kernel(const float* __restrict__ pk, uint32_t* __restrict__ ks) {
    int p = blockIdx.x * 256 + threadIdx.x;
    int row = p >> 5, dg = p & 31;
    float2 v = *(const float2*)&pk[(size_t)row * HD + dg * 2];
    uint32_t hi, lo;
    split2(v.x, v.y, hi, lo);
    ks[(size_t)row * 64 + dg] = hi;
    ks[(size_t)row * 64 + 32 + dg] = lo;
}

// ---------------- split V^T for attention ----------------
__global__ void split_vt_kernel(const float* __restrict__ pv,
                                uint32_t* __restrict__ vthi, uint32_t* __restrict__ vtlo) {
    int p = blockIdx.x * 256 + threadIdx.x;
    int kvh = p >> 16, rem = p & 65535;
    int sp = rem >> 6, d = rem & 63;
    float v0 = pv[((size_t)kvh * SEQ + 2 * sp) * HD + d];
    float v1 = pv[((size_t)kvh * SEQ + 2 * sp + 1) * HD + d];
    uint32_t hi, lo;
    split2(v0, v1, hi, lo);
    vthi[((size_t)kvh * 64 + d) * (SEQ / 2) + sp] = hi;
    vtlo[((size_t)kvh * 64 + d) * (SEQ / 2) + sp] = lo;
}

// ---------------- tensor-core flash attention -> fragment image ----------------
__global__ __launch_bounds__(256) void attn_mma_kernel(const float* __restrict__ q,
                                                       const uint32_t* __restrict__ Ks,
                                                       const uint32_t* __restrict__ Vthi,
                                                       const uint32_t* __restrict__ Vtlo,
                                                       uint32_t* __restrict__ oimg) {
    __shared__ uint32_t KHi[64 * 36], KLo[64 * 36];
    __shared__ uint32_t VHi[64 * 36], VLo[64 * 36];

    int qb = blockIdx.x, h = blockIdx.y, kvh = h >> 2;
    int tid = threadIdx.x, w = tid >> 5, lane = tid & 31;
    int gid = lane >> 2, tig = lane & 3;

    uint32_t qh[4][4], ql[4][4];
    int rmin = qb * 128 + w * 16;
    {
        const float* q0 = q + (size_t)(rmin + gid) * QKVN + h * HD;
        const float* q1 = q0 + 8 * QKVN;
#pragma unroll
        for (int c = 0; c < 4; c++) {
            float2 x0 = *(const float2*)(q0 + c * 16 + tig * 2);
            float2 x1 = *(const float2*)(q1 + c * 16 + tig * 2);
            float2 x2 = *(const float2*)(q0 + c * 16 + 8 + tig * 2);
            float2 x3 = *(const float2*)(q1 + c * 16 + 8 + tig * 2);
            split2(x0.x * 0.125f, x0.y * 0.125f, qh[c][0], ql[c][0]);
            split2(x1.x * 0.125f, x1.y * 0.125f, qh[c][1], ql[c][1]);
            split2(x2.x * 0.125f, x2.y * 0.125f, qh[c][2], ql[c][2]);
            split2(x3.x * 0.125f, x3.y * 0.125f, qh[c][3], ql[c][3]);
        }
    }

    float m0 = -1e30f, m1 = -1e30f, l0 = 0.f, l1 = 0.f;
    float acc[8][4];
#pragma unroll
    for (int nb = 0; nb < 8; nb++)
#pragma unroll
        for (int r = 0; r < 4; r++) acc[nb][r] = 0.f;

    int ktend = 2 * qb + 1;
    for (int kt = 0; kt <= ktend; kt++) {
#pragma unroll
        for (int i = 0; i < 4; i++) {
            int c0 = tid + i * 256;
            int row = c0 >> 4, part = c0 & 15;
            const uint32_t* src = Ks + ((size_t)(kvh * SEQ + kt * 64 + row)) * 64
                                  + ((part >> 3) * 32) + ((part & 7) * 4);
            uint32_t* dst = ((part >> 3) ? KLo : KHi) + row * 36 + (part & 7) * 4;
            cp_async16(dst, src);
        }
#pragma unroll
        for (int i = 0; i < 4; i++) {
            int c0 = tid + i * 256;
            int d = c0 >> 4, part = c0 & 15;
            const uint32_t* src = ((part >> 3) ? Vtlo : Vthi)
                                  + ((size_t)kvh * 64 + d) * (SEQ / 2) + kt * 32 + (part & 7) * 4;
            uint32_t* dst = ((part >> 3) ? VLo : VHi) + d * 36 + (part & 7) * 4;
            cp_async16(dst, src);
        }
        CP_COMMIT();
        CP_WAIT0();
        __syncthreads();

        bool skip = (kt * 64 > rmin + 15);
        if (!skip) {
            float sc[8][4];
#pragma unroll
            for (int nb = 0; nb < 8; nb++)
#pragma unroll
                for (int r = 0; r < 4; r++) sc[nb][r] = 0.f;

#pragma unroll
            for (int c = 0; c < 4; c++) {
#pragma unroll
                for (int nb = 0; nb < 8; nb++) {
                    int srow = (nb * 8 + gid) * 36 + c * 8 + tig;
                    uint32_t bh[2] = {KHi[srow], KHi[srow + 4]};
                    uint32_t bl[2] = {KLo[srow], KLo[srow + 4]};
                    mma_bf16(sc[nb], qh[c], bl);
                    mma_bf16(sc[nb], ql[c], bh);
                    mma_bf16(sc[nb], qh[c], bh);
                }
            }

            if (kt * 64 + 63 > rmin) {
                int r0 = rmin + gid, r1 = rmin + 8 + gid;
#pragma unroll
                for (int nb = 0; nb < 8; nb++) {
#pragma unroll
                    for (int j = 0; j < 2; j++) {
                        int col = kt * 64 + nb * 8 + tig * 2 + j;
                        if (col > r0) sc[nb][j] = -1e30f;
                        if (col > r1) sc[nb][2 + j] = -1e30f;
                    }
                }
            }

            float mx0 = -1e30f, mx1 = -1e30f;
#pragma unroll
            for (int nb = 0; nb < 8; nb++) {
                mx0 = fmaxf(mx0, fmaxf(sc[nb][0], sc[nb][1]));
                mx1 = fmaxf(mx1, fmaxf(sc[nb][2], sc[nb][3]));
            }
            mx0 = fmaxf(mx0, __shfl_xor_sync(0xffffffffu, mx0, 1));
            mx0 = fmaxf(mx0, __shfl_xor_sync(0xffffffffu, mx0, 2));
            mx1 = fmaxf(mx1, __shfl_xor_sync(0xffffffffu, mx1, 1));
            mx1 = fmaxf(mx1, __shfl_xor_sync(0xffffffffu, mx1, 2));
            float mn0 = fmaxf(m0, mx0), mn1 = fmaxf(m1, mx1);
            float al0 = __expf(m0 - mn0), al1 = __expf(m1 - mn1);
            float s0 = 0.f, s1 = 0.f;
#pragma unroll
            for (int nb = 0; nb < 8; nb++) {
                sc[nb][0] = __expf(sc[nb][0] - mn0);
                sc[nb][1] = __expf(sc[nb][1] - mn0);
                sc[nb][2] = __expf(sc[nb][2] - mn1);
                sc[nb][3] = __expf(sc[nb][3] - mn1);
                s0 += sc[nb][0] + sc[nb][1];
                s1 += sc[nb][2] + sc[nb][3];
            }
            s0 += __shfl_xor_sync(0xffffffffu, s0, 1);
            s0 += __shfl_xor_sync(0xffffffffu, s0, 2);
            s1 += __shfl_xor_sync(0xffffffffu, s1, 1);
            s1 += __shfl_xor_sync(0xffffffffu, s1, 2);
            l0 = l0 * al0 + s0; m0 = mn0;
            l1 = l1 * al1 + s1; m1 = mn1;
#pragma unroll
            for (int nb = 0; nb < 8; nb++) {
                acc[nb][0] *= al0; acc[nb][1] *= al0;
                acc[nb][2] *= al1; acc[nb][3] *= al1;
            }

#pragma unroll
            for (int c = 0; c < 4; c++) {
                uint32_t ah[4], al_[4];
                split2(sc[2 * c][0],     sc[2 * c][1],     ah[0], al_[0]);
                split2(sc[2 * c][2],     sc[2 * c][3],     ah[1], al_[1]);
                split2(sc[2 * c + 1][0], sc[2 * c + 1][1], ah[2], al_[2]);
                split2(sc[2 * c + 1][2], sc[2 * c + 1][3], ah[3], al_[3]);
#pragma unroll
                for (int nb = 0; nb < 8; nb++) {
                    int drow = (nb * 8 + gid) * 36 + c * 8 + tig;
                    uint32_t bh[2] = {VHi[drow], VHi[drow + 4]};
                    uint32_t bl[2] = {VLo[drow], VLo[drow + 4]};
                    mma_bf16(acc[nb], ah, bl);
                    mma_bf16(acc[nb], al_, bh);
                    mma_bf16(acc[nb], ah, bh);
                }
            }
        }
        __syncthreads();
    }

    float inv0 = 1.f / l0, inv1 = 1.f / l1;
    int row0 = rmin + gid;
#pragma unroll
    for (int nb = 0; nb < 8; nb++) {
        int col = h * HD + nb * 8 + tig * 2;
        store_frag(oimg, HDIM / 32, row0, col, acc[nb][0] * inv0, acc[nb][1] * inv0);
        store_frag(oimg, HDIM / 32, row0 + 8, col, acc[nb][2] * inv1, acc[nb][3] * inv1);
    }
}

// ---------------- silu(g) * u -> fragment image ----------------
__global__ void silu_mul_frag_kernel(const float* __restrict__ gu,
                                     uint32_t* __restrict__ img) {
    int p = blockIdx.x * 256 + threadIdx.x;   // pair index, SEQ*IDIM/2 total
    int s = p >> 11, c = (p & 2047) << 1;
    const float* row = gu + (size_t)s * GUN;
    float2 g = *(const float2*)(row + c);
    float2 u = *(const float2*)(row + IDIM + c);
    float a = g.x / (1.f + __expf(-g.x)) * u.x;
    float b = g.y / (1.f + __expf(-g.y)) * u.y;
    store_frag(img, IDIM / 32, s, c, a, b);
}

// ---------------- host launch ----------------
extern "C" void kernel_launch(void* const* d_in, const int* in_sizes, int n_in,
                              void* d_out, int out_size) {
    (void)in_sizes; (void)n_in; (void)out_size;

    static bool init = false;
    static float *p_h, *p_qkv, *p_gu;
    static uint32_t *p_wqkv, *p_wo, *p_wgu, *p_wdown, *p_wlm;
    static uint32_t *p_ks, *p_vthi, *p_vtlo, *p_aimg;
    if (!init) {
        cudaGetSymbolAddress((void**)&p_h, g_h);
        cudaGetSymbolAddress((void**)&p_qkv, g_qkv);
        cudaGetSymbolAddress((void**)&p_gu, g_gu);
        cudaGetSymbolAddress((void**)&p_wqkv, wp_qkv);
        cudaGetSymbolAddress((void**)&p_wo, wp_o);
        cudaGetSymbolAddress((void**)&p_wgu, wp_gu);
        cudaGetSymbolAddress((void**)&p_wdown, wp_down);
        cudaGetSymbolAddress((void**)&p_wlm, wp_lm);
        cudaGetSymbolAddress((void**)&p_ks, g_ks);
        cudaGetSymbolAddress((void**)&p_vthi, g_vthi);
        cudaGetSymbolAddress((void**)&p_vtlo, g_vtlo);
        cudaGetSymbolAddress((void**)&p_aimg, g_aimg);
        init = true;
    }

    const int*   ids    = (const int*)d_in[0];
    const int*   pos    = (const int*)d_in[1];
    const float* audio  = (const float*)d_in[2];
    const int*   aoff   = (const int*)d_in[3];
    const float* embw   = (const float*)d_in[4];
    const float* q_w    = (const float*)d_in[5];
    const float* k_w    = (const float*)d_in[6];
    const float* v_w    = (const float*)d_in[7];
    const float* o_w    = (const float*)d_in[8];
    const float* qn_w   = (const float*)d_in[9];
    const float* kn_w   = (const float*)d_in[10];
    const float* ln1_w  = (const float*)d_in[11];
    const float* ln2_w  = (const float*)d_in[12];
    const float* gate_w = (const float*)d_in[13];
    const float* up_w   = (const float*)d_in[14];
    const float* down_w = (const float*)d_in[15];
    const float* norm_w = (const float*)d_in[16];
    const float* lm_w   = (const float*)d_in[17];

    float* out    = (float*)d_out;
    float* logits = out;
    float* pk     = out + (size_t)SEQ * VOCAB;
    float* pv     = pk + (size_t)NLAYER * NKV * SEQ * HD;

    const int BIG = 1 << 30;

    for (int l = 0; l < NLAYER; l++) {
        prep_w_kernel<<<dim3(QKVN / 128, HDIM / 32), 256>>>(
            q_w + (size_t)l * HDIM * (NH * HD), NH * HD,
            k_w + (size_t)l * HDIM * (NKV * HD), NKV * HD,
            v_w + (size_t)l * HDIM * (NKV * HD), NKV * HD,
            NH * HD, NH * HD + NKV * HD,
            p_wqkv + (size_t)l * HDIM * QKVN);
        prep_w_kernel<<<dim3(HDIM / 128, HDIM / 32), 256>>>(
            o_w + (size_t)l * HDIM * HDIM, HDIM, o_w, HDIM, o_w, HDIM, BIG, BIG,
            p_wo + (size_t)l * HDIM * HDIM);
        prep_w_kernel<<<dim3(GUN / 128, HDIM / 32), 256>>>(
            gate_w + (size_t)l * HDIM * IDIM, IDIM,
            up_w + (size_t)l * HDIM * IDIM, IDIM,
            up_w, IDIM, IDIM, BIG,
            p_wgu + (size_t)l * HDIM * GUN);
        prep_w_kernel<<<dim3(HDIM / 128, IDIM / 32), 256>>>(
            down_w + (size_t)l * IDIM * HDIM, HDIM, down_w, HDIM, down_w, HDIM, BIG, BIG,
            p_wdown + (size_t)l * IDIM * HDIM);
    }
    prep_w_kernel<<<dim3(VOCAB / 128, HDIM / 32), 256>>>(
        lm_w, VOCAB, lm_w, VOCAB, lm_w, VOCAB, BIG, BIG, p_wlm);

    embed_scatter_kernel<<<SEQ, 256>>>(ids, embw, audio, aoff, p_h);

    for (int l = 0; l < NLAYER; l++) {
        float* pk_l = pk + (size_t)l * NKV * SEQ * HD;
        float* pv_l = pv + (size_t)l * NKV * SEQ * HD;

        rmsnorm_frag_kernel<<<SEQ, 256>>>(p_h, ln1_w + (size_t)l * HDIM, p_aimg);
        gemm_bf16x2_kernel<<<dim3(QKVN / 128, SEQ / 128), 256>>>(
            p_aimg, p_wqkv + (size_t)l * HDIM * QKVN, nullptr, p_qkv, SEQ, QKVN, HDIM);

        rms_rope_kernel<<<dim3(SEQ, 4), 128>>>(p_qkv, QKVN, qn_w + (size_t)l * HD, pos,
                                               p_qkv, nullptr, NH);
        rms_rope_kernel<<<dim3(SEQ, 1), 128>>>(p_qkv + NH * HD, QKVN, kn_w + (size_t)l * HD, pos,
                                               nullptr, pk_l, NKV);
        copy_v_kernel<<<SEQ, 256>>>(p_qkv, pv_l);

        split_k_kernel<<<NKV * SEQ * 32 / 256, 256>>>(pk_l, p_ks);
        split_vt_kernel<<<NKV * 64 * (SEQ / 2) / 256, 256>>>(pv_l, p_vthi, p_vtlo);

        attn_mma_kernel<<<dim3(SEQ / 128, NH), 256>>>(p_qkv, p_ks, p_vthi, p_vtlo, p_aimg);

        gemm_bf16x2_kernel<<<dim3(HDIM / 128, SEQ / 128), 256>>>(
            p_aimg, p_wo + (size_t)l * HDIM * HDIM, p_h, p_h, SEQ, HDIM, HDIM);

        rmsnorm_frag_kernel<<<SEQ, 256>>>(p_h, ln2_w + (size_t)l * HDIM, p_aimg);
        gemm_bf16x2_kernel<<<dim3(GUN / 128, SEQ / 128), 256>>>(
            p_aimg, p_wgu + (size_t)l * HDIM * GUN, nullptr, p_gu, SEQ, GUN, HDIM);

        silu_mul_frag_kernel<<<(SEQ * IDIM / 2) / 256, 256>>>(p_gu, p_aimg);
        gemm_bf16x2_kernel<<<dim3(HDIM / 128, SEQ / 128), 256>>>(
            p_aimg, p_wdown + (size_t)l * IDIM * HDIM, p_h, p_h, SEQ, HDIM, IDIM);
    }

    rmsnorm_frag_kernel<<<SEQ, 256>>>(p_h, norm_w, p_aimg);
    gemm_bf16x2_kernel<<<dim3(VOCAB / 128, SEQ / 128), 256>>>(
        p_aimg, p_wlm, nullptr, logits, SEQ, VOCAB, HDIM);
}

// round 16
// speedup vs baseline: 1.9463x; 1.0011x over previous
#include <cuda_runtime.h>
#include <cuda_bf16.h>
#include <stdint.h>
#include <math.h>

#define SEQ 2048
#define HDIM 1024
#define NLAYER 4
#define NH 16
#define NKV 4
#define HD 64
#define IDIM 4096
#define VOCAB 32000
#define QKVN 1536
#define GUN 8192

// ---------------- scratch ----------------
__device__ float g_h[SEQ * HDIM];
__device__ float g_qkv[SEQ * QKVN];
__device__ float g_gu[SEQ * GUN];

// activation fragment image (legacy mma layout), max 2048 x 4096
__device__ uint32_t g_aimg[SEQ * IDIM];

// weight images (fragment-slot bf16 hi/lo, 1 uint32/elem)
__device__ uint32_t wp_qkv[NLAYER * HDIM * QKVN];
__device__ uint32_t wp_o[NLAYER * HDIM * HDIM];
__device__ uint32_t wp_gu[NLAYER * HDIM * GUN];
__device__ uint32_t wp_down[NLAYER * IDIM * HDIM];
__device__ uint32_t wp_lm[HDIM * VOCAB];

// pre-split attention operands (per current layer)
__device__ uint32_t g_ks[NKV * SEQ * 64];
__device__ uint32_t g_vthi[NKV * 64 * (SEQ / 2)];
__device__ uint32_t g_vtlo[NKV * 64 * (SEQ / 2)];

// ---------------- helpers ----------------
__device__ __forceinline__ void split2(float x, float y, uint32_t& hi, uint32_t& lo) {
    __nv_bfloat162 h = __floats2bfloat162_rn(x, y);
    hi = *(uint32_t*)&h;
    __nv_bfloat162 l = __floats2bfloat162_rn(x - __bfloat162float(h.x),
                                             y - __bfloat162float(h.y));
    lo = *(uint32_t*)&l;
}

// per-element bf16 hi/lo halves (independent of pairing)
__device__ __forceinline__ void split1(float x, __nv_bfloat16& hi, __nv_bfloat16& lo) {
    hi = __float2bfloat16_rn(x);
    lo = __float2bfloat16_rn(x - __bfloat162float(hi));
}

// write one (row, k..k+1) fp32 pair into the A fragment image (k even)
__device__ __forceinline__ void store_frag(uint32_t* __restrict__ img, int KT,
                                           int row, int k, float x, float y) {
    int mt = row >> 7, rl = row & 127;
    int kc = k >> 5, kl = k & 31;
    int lane = ((rl & 7) << 2) | ((kl >> 1) & 3);
    int reg = (((kl >> 3) & 1) << 1) | ((rl >> 3) & 1);
    int v = ((kl >> 4) << 3) | (rl >> 4);
    size_t base = ((size_t)mt * KT + kc) * 4096 + v * 256 + lane * 4 + reg;
    uint32_t hi, lo;
    split2(x, y, hi, lo);
    img[base] = hi;
    img[base + 128] = lo;
}

__device__ __forceinline__ void mma_bf16(float* c, const uint32_t* a, const uint32_t* b) {
    asm volatile(
        "mma.sync.aligned.m16n8k16.row.col.f32.bf16.bf16.f32 "
        "{%0,%1,%2,%3}, {%4,%5,%6,%7}, {%8,%9}, {%0,%1,%2,%3};"
        : "+f"(c[0]), "+f"(c[1]), "+f"(c[2]), "+f"(c[3])
        : "r"(a[0]), "r"(a[1]), "r"(a[2]), "r"(a[3]), "r"(b[0]), "r"(b[1]));
}

__device__ __forceinline__ void cp_async16(void* smem, const void* gmem) {
    uint32_t s = (uint32_t)__cvta_generic_to_shared(smem);
    asm volatile("cp.async.cg.shared.global [%0], [%1], 16;" :: "r"(s), "l"(gmem));
}
#define CP_COMMIT() asm volatile("cp.async.commit_group;")
#define CP_WAIT0()  asm volatile("cp.async.wait_group 0;")

// ---------------- weight prep: [K][N] f32 -> fragment-ordered bf16 hi/lo ----------------
__global__ void prep_w_kernel(const float* __restrict__ s0, int st0,
                              const float* __restrict__ s1, int st1,
                              const float* __restrict__ s2, int st2,
                              int n1, int n2, uint32_t* __restrict__ out) {
    int kt = blockIdx.y, nt = blockIdx.x, NT = gridDim.x;
    int t = threadIdx.x;
#pragma unroll
    for (int it = 0; it < 4; it++) {
        int slot = it * 256 + t;
        int lane = slot & 31, in = (slot >> 5) & 15, ik = slot >> 9;
        int g = lane >> 2, c = lane & 3;
        int n = nt * 128 + in * 8 + g;
        int kb = kt * 32 + ik * 16 + 2 * c;
        const float* src; int nn; int st;
        if (n >= n2)      { src = s2; nn = n - n2; st = st2; }
        else if (n >= n1) { src = s1; nn = n - n1; st = st1; }
        else              { src = s0; nn = n;      st = st0; }
        float x0 = src[(size_t)(kb + 0) * st + nn];
        float x1 = src[(size_t)(kb + 1) * st + nn];
        float x8 = src[(size_t)(kb + 8) * st + nn];
        float x9 = src[(size_t)(kb + 9) * st + nn];
        uint4 o;
        uint32_t l01, l89;
        split2(x0, x1, o.x, l01);
        split2(x8, x9, o.y, l89);
        o.z = l01; o.w = l89;
        *(uint4*)&out[((size_t)((size_t)kt * NT + nt) * 1024 + slot) * 4] = o;
    }
}

// ---------------- bf16x2 (3-term) tensor-core GEMM, all-cp.async mainloop ----------------
__global__ __launch_bounds__(256) void gemm_bf16x2_kernel(
    const uint32_t* __restrict__ Aimg, const uint32_t* __restrict__ Bp,
    const float* __restrict__ Res, float* __restrict__ C,
    int M, int N, int K) {
    __shared__ uint32_t Asm[2][4096];
    __shared__ uint32_t Bsm[2][4096];

    int tid = threadIdx.x, lane = tid & 31, warp = tid >> 5;
    int wm = warp >> 2, wn = warp & 3;
    int bnx = blockIdx.x, mt = blockIdx.y;
    int NT = N >> 7, KT = K >> 5;

    float acc[4][4][4];
#pragma unroll
    for (int im = 0; im < 4; im++)
#pragma unroll
        for (int in = 0; in < 4; in++)
#pragma unroll
            for (int r = 0; r < 4; r++) acc[im][in][r] = 0.f;

#define CPAB(kt, st)                                                                 \
    {                                                                                \
        const uint32_t* aS = Aimg + ((size_t)mt * KT + (kt)) * 4096;                 \
        const uint32_t* bS = Bp + ((size_t)(kt) * NT + bnx) * 4096;                  \
        _Pragma("unroll")                                                            \
        for (int i = 0; i < 4; i++) {                                                \
            int s4 = tid + i * 256;                                                  \
            cp_async16(&Asm[st][s4 * 4], aS + s4 * 4);                               \
            cp_async16(&Bsm[st][s4 * 4], bS + s4 * 4);                               \
        }                                                                            \
    }

#define COMPUTE(st)                                                                  \
    {                                                                                \
        _Pragma("unroll")                                                            \
        for (int ik = 0; ik < 2; ik++) {                                             \
            uint32_t ah[4][4], al[4][4], bh[4][2], bl[4][2];                         \
            _Pragma("unroll")                                                        \
            for (int im = 0; im < 4; im++) {                                         \
                *(uint4*)ah[im] = *(const uint4*)&Asm[st][(((ik * 8 + wm * 4 + im) * 2 + 0) * 32 + lane) * 4]; \
                *(uint4*)al[im] = *(const uint4*)&Asm[st][(((ik * 8 + wm * 4 + im) * 2 + 1) * 32 + lane) * 4]; \
            }                                                                        \
            _Pragma("unroll")                                                        \
            for (int in = 0; in < 4; in++) {                                         \
                uint4 qv = *(const uint4*)&Bsm[st][((ik * 16 + wn * 4 + in) * 32 + lane) * 4]; \
                bh[in][0] = qv.x; bh[in][1] = qv.y;                                  \
                bl[in][0] = qv.z; bl[in][1] = qv.w;                                  \
            }                                                                        \
            _Pragma("unroll")                                                        \
            for (int im = 0; im < 4; im++)                                           \
                _Pragma("unroll")                                                    \
                for (int in = 0; in < 4; in++) {                                     \
                    mma_bf16(acc[im][in], ah[im], bl[in]);                           \
                    mma_bf16(acc[im][in], al[im], bh[in]);                           \
                    mma_bf16(acc[im][in], ah[im], bh[in]);                           \
                }                                                                    \
        }                                                                            \
    }

    CPAB(0, 0); CP_COMMIT();
    CP_WAIT0();
    __syncthreads();

    for (int kt = 0; kt < KT; kt++) {
        int st = kt & 1;
        if (kt + 1 < KT) { CPAB(kt + 1, st ^ 1); CP_COMMIT(); }
        COMPUTE(st);
        if (kt + 1 < KT) { CP_WAIT0(); }
        __syncthreads();
    }

    int gid = lane >> 2, tig = lane & 3;
#pragma unroll
    for (int im = 0; im < 4; im++) {
#pragma unroll
        for (int in = 0; in < 4; in++) {
            int row0 = mt * 128 + wm * 64 + im * 16 + gid;
            int col = bnx * 128 + wn * 32 + in * 8 + tig * 2;
            float2 v0 = make_float2(acc[im][in][0], acc[im][in][1]);
            float2 v1 = make_float2(acc[im][in][2], acc[im][in][3]);
            if (Res) {
                float2 r0 = *(const float2*)(Res + (size_t)row0 * N + col);
                float2 r1 = *(const float2*)(Res + (size_t)(row0 + 8) * N + col);
                v0.x += r0.x; v0.y += r0.y;
                v1.x += r1.x; v1.y += r1.y;
            }
            *(float2*)(C + (size_t)row0 * N + col) = v0;
            *(float2*)(C + (size_t)(row0 + 8) * N + col) = v1;
        }
    }
#undef CPAB
#undef COMPUTE
}

// ---------------- embedding + audio scatter ----------------
__global__ void embed_scatter_kernel(const int* __restrict__ ids,
                                     const float* __restrict__ emb,
                                     const float* __restrict__ audio,
                                     const int* __restrict__ aoff,
                                     float* __restrict__ h) {
    int s = blockIdx.x;
    int off = aoff[0];
    const float* src;
    if (s >= off && s < off + 256) src = audio + (size_t)(s - off) * HDIM;
    else                           src = emb + (size_t)ids[s] * HDIM;
    float* dst = h + (size_t)s * HDIM;
    int i = threadIdx.x * 4;
    *(float4*)&dst[i] = *(const float4*)&src[i];
}

// ---------------- RMSNorm H=1024 -> fragment image ----------------
__global__ void rmsnorm_frag_kernel(const float* __restrict__ x,
                                    const float* __restrict__ w,
                                    uint32_t* __restrict__ img) {
    int s = blockIdx.x;
    const float* xr = x + (size_t)s * HDIM;
    float ss = 0.f;
#pragma unroll
    for (int i = 0; i < 4; i++) { float v = xr[threadIdx.x + i * 256]; ss += v * v; }
    __shared__ float red[8];
#pragma unroll
    for (int o = 16; o; o >>= 1) ss += __shfl_xor_sync(0xffffffffu, ss, o);
    if ((threadIdx.x & 31) == 0) red[threadIdx.x >> 5] = ss;
    __syncthreads();
    if (threadIdx.x < 32) {
        float v = (threadIdx.x < 8) ? red[threadIdx.x] : 0.f;
#pragma unroll
        for (int o = 4; o; o >>= 1) v += __shfl_xor_sync(0xffffffffu, v, o);
        if (threadIdx.x == 0) red[0] = v;
    }
    __syncthreads();
    float r = rsqrtf(red[0] * (1.f / HDIM) + 1e-6f);
#pragma unroll
    for (int i = 0; i < 2; i++) {
        int k = 2 * threadIdx.x + i * 512;
        float a = xr[k] * r * w[k];
        float b = xr[k + 1] * r * w[k + 1];
        store_frag(img, HDIM / 32, s, k, a, b);
    }
}

// ---------------- fused QKV post-process ----------------
// grid (SEQ, 5), 128 threads.
// blockIdx.y<4: q-head rms+rope (h = y*4 + warp), write back into g_qkv.
// blockIdx.y==4: k rms+rope -> pk_l + g_ks (16-bit split stores);
//                v copy -> pv_l + g_vthi/g_vtlo (16-bit split stores).
__global__ void rope_fused_kernel(float* __restrict__ qkv,
                                  const float* __restrict__ qn_w,
                                  const float* __restrict__ kn_w,
                                  const int* __restrict__ pos_ids,
                                  float* __restrict__ pk_l,
                                  float* __restrict__ pv_l,
                                  uint32_t* __restrict__ ks,
                                  uint32_t* __restrict__ vthi,
                                  uint32_t* __restrict__ vtlo) {
    int s = blockIdx.x;
    int warp = threadIdx.x >> 5, lane = threadIdx.x & 31;
    float pos = (float)pos_ids[s];
    float invf = expf(-((float)lane * (1.f / 32.f)) * 9.210340371976184f);
    float ang = pos * invf;
    float c, sn;
    sincosf(ang, &sn, &c);

    if (blockIdx.y < 4) {
        int h = blockIdx.y * 4 + warp;
        float* x = qkv + (size_t)s * QKVN + h * HD;
        float x0 = x[lane], x1 = x[lane + 32];
        float ss = x0 * x0 + x1 * x1;
#pragma unroll
        for (int o = 16; o; o >>= 1) ss += __shfl_xor_sync(0xffffffffu, ss, o);
        float r = rsqrtf(ss * (1.f / HD) + 1e-6f);
        x0 = x0 * r * qn_w[lane];
        x1 = x1 * r * qn_w[lane + 32];
        float o0 = x0 * c - x1 * sn;
        float o1 = x1 * c + x0 * sn;
        x[lane] = o0; x[lane + 32] = o1;
    } else {
        // K: warp = kvh
        int kvh = warp;
        const float* x = qkv + (size_t)s * QKVN + NH * HD + kvh * HD;
        float x0 = x[lane], x1 = x[lane + 32];
        float ss = x0 * x0 + x1 * x1;
#pragma unroll
        for (int o = 16; o; o >>= 1) ss += __shfl_xor_sync(0xffffffffu, ss, o);
        float r = rsqrtf(ss * (1.f / HD) + 1e-6f);
        x0 = x0 * r * kn_w[lane];
        x1 = x1 * r * kn_w[lane + 32];
        float o0 = x0 * c - x1 * sn;
        float o1 = x1 * c + x0 * sn;
        size_t row = (size_t)kvh * SEQ + s;
        float* pp = pk_l + row * HD;
        pp[lane] = o0; pp[lane + 32] = o1;
        // ks split: u16 layout [row][hi d0..63 | lo d0..63]
        __nv_bfloat16* k16 = (__nv_bfloat16*)(ks + row * 64);
        __nv_bfloat16 h0, l0, h1, l1;
        split1(o0, h0, l0);
        split1(o1, h1, l1);
        k16[lane] = h0;       k16[lane + 32] = h1;
        k16[64 + lane] = l0;  k16[64 + lane + 32] = l1;

        // V: 256 elems, 2 per thread
        int sp = s >> 1, sb = s & 1;
#pragma unroll
        for (int i = 0; i < 2; i++) {
            int e = threadIdx.x + i * 128;
            int kv = e >> 6, d = e & 63;
            float v = qkv[(size_t)s * QKVN + (NH + NKV) * HD + e];
            pv_l[((size_t)kv * SEQ + s) * HD + d] = v;
            __nv_bfloat16 vh, vl;
            split1(v, vh, vl);
            size_t w16 = (((size_t)kv * 64 + d) * (SEQ / 2) + sp);
            ((__nv_bfloat16*)vthi)[w16 * 2 + sb] = vh;
            ((__nv_bfloat16*)vtlo)[w16 * 2 + sb] = vl;
        }
    }
}

// ---------------- tensor-core flash attention -> fragment image ----------------
__global__ __launch_bounds__(256) void attn_mma_kernel(const float* __restrict__ q,
                                                       const uint32_t* __restrict__ Ks,
                                                       const uint32_t* __restrict__ Vthi,
                                                       const uint32_t* __restrict__ Vtlo,
                                                       uint32_t* __restrict__ oimg) {
    __shared__ uint32_t KHi[64 * 36], KLo[64 * 36];
    __shared__ uint32_t VHi[64 * 36], VLo[64 * 36];

    int qb = blockIdx.x, h = blockIdx.y, kvh = h >> 2;
    int tid = threadIdx.x, w = tid >> 5, lane = tid & 31;
    int gid = lane >> 2, tig = lane & 3;

    uint32_t qh[4][4], ql[4][4];
    int rmin = qb * 128 + w * 16;
    {
        const float* q0 = q + (size_t)(rmin + gid) * QKVN + h * HD;
        const float* q1 = q0 + 8 * QKVN;
#pragma unroll
        for (int c = 0; c < 4; c++) {
            float2 x0 = *(const float2*)(q0 + c * 16 + tig * 2);
            float2 x1 = *(const float2*)(q1 + c * 16 + tig * 2);
            float2 x2 = *(const float2*)(q0 + c * 16 + 8 + tig * 2);
            float2 x3 = *(const float2*)(q1 + c * 16 + 8 + tig * 2);
            split2(x0.x * 0.125f, x0.y * 0.125f, qh[c][0], ql[c][0]);
            split2(x1.x * 0.125f, x1.y * 0.125f, qh[c][1], ql[c][1]);
            split2(x2.x * 0.125f, x2.y * 0.125f, qh[c][2], ql[c][2]);
            split2(x3.x * 0.125f, x3.y * 0.125f, qh[c][3], ql[c][3]);
        }
    }

    float m0 = -1e30f, m1 = -1e30f, l0 = 0.f, l1 = 0.f;
    float acc[8][4];
#pragma unroll
    for (int nb = 0; nb < 8; nb++)
#pragma unroll
        for (int r = 0; r < 4; r++) acc[nb][r] = 0.f;

    int ktend = 2 * qb + 1;
    for (int kt = 0; kt <= ktend; kt++) {
#pragma unroll
        for (int i = 0; i < 4; i++) {
            int c0 = tid + i * 256;
            int row = c0 >> 4, part = c0 & 15;
            const uint32_t* src = Ks + ((size_t)(kvh * SEQ + kt * 64 + row)) * 64
                                  + ((part >> 3) * 32) + ((part & 7) * 4);
            uint32_t* dst = ((part >> 3) ? KLo : KHi) + row * 36 + (part & 7) * 4;
            cp_async16(dst, src);
        }
#pragma unroll
        for (int i = 0; i < 4; i++) {
            int c0 = tid + i * 256;
            int d = c0 >> 4, part = c0 & 15;
            const uint32_t* src = ((part >> 3) ? Vtlo : Vthi)
                                  + ((size_t)kvh * 64 + d) * (SEQ / 2) + kt * 32 + (part & 7) * 4;
            uint32_t* dst = ((part >> 3) ? VLo : VHi) + d * 36 + (part & 7) * 4;
            cp_async16(dst, src);
        }
        CP_COMMIT();
        CP_WAIT0();
        __syncthreads();

        bool skip = (kt * 64 > rmin + 15);
        if (!skip) {
            float sc[8][4];
#pragma unroll
            for (int nb = 0; nb < 8; nb++)
#pragma unroll
                for (int r = 0; r < 4; r++) sc[nb][r] = 0.f;

#pragma unroll
            for (int c = 0; c < 4; c++) {
#pragma unroll
                for (int nb = 0; nb < 8; nb++) {
                    int srow = (nb * 8 + gid) * 36 + c * 8 + tig;
                    uint32_t bh[2] = {KHi[srow], KHi[srow + 4]};
                    uint32_t bl[2] = {KLo[srow], KLo[srow + 4]};
                    mma_bf16(sc[nb], qh[c], bl);
                    mma_bf16(sc[nb], ql[c], bh);
                    mma_bf16(sc[nb], qh[c], bh);
                }
            }

            if (kt * 64 + 63 > rmin) {
                int r0 = rmin + gid, r1 = rmin + 8 + gid;
#pragma unroll
                for (int nb = 0; nb < 8; nb++) {
#pragma unroll
                    for (int j = 0; j < 2; j++) {
                        int col = kt * 64 + nb * 8 + tig * 2 + j;
                        if (col > r0) sc[nb][j] = -1e30f;
                        if (col > r1) sc[nb][2 + j] = -1e30f;
                    }
                }
            }

            float mx0 = -1e30f, mx1 = -1e30f;
#pragma unroll
            for (int nb = 0; nb < 8; nb++) {
                mx0 = fmaxf(mx0, fmaxf(sc[nb][0], sc[nb][1]));
                mx1 = fmaxf(mx1, fmaxf(sc[nb][2], sc[nb][3]));
            }
            mx0 = fmaxf(mx0, __shfl_xor_sync(0xffffffffu, mx0, 1));
            mx0 = fmaxf(mx0, __shfl_xor_sync(0xffffffffu, mx0, 2));
            mx1 = fmaxf(mx1, __shfl_xor_sync(0xffffffffu, mx1, 1));
            mx1 = fmaxf(mx1, __shfl_xor_sync(0xffffffffu, mx1, 2));
            float mn0 = fmaxf(m0, mx0), mn1 = fmaxf(m1, mx1);
            float al0 = __expf(m0 - mn0), al1 = __expf(m1 - mn1);
            float s0 = 0.f, s1 = 0.f;
#pragma unroll
            for (int nb = 0; nb < 8; nb++) {
                sc[nb][0] = __expf(sc[nb][0] - mn0);
                sc[nb][1] = __expf(sc[nb][1] - mn0);
                sc[nb][2] = __expf(sc[nb][2] - mn1);
                sc[nb][3] = __expf(sc[nb][3] - mn1);
                s0 += sc[nb][0] + sc[nb][1];
                s1 += sc[nb][2] + sc[nb][3];
            }
            s0 += __shfl_xor_sync(0xffffffffu, s0, 1);
            s0 += __shfl_xor_sync(0xffffffffu, s0, 2);
            s1 += __shfl_xor_sync(0xffffffffu, s1, 1);
            s1 += __shfl_xor_sync(0xffffffffu, s1, 2);
            l0 = l0 * al0 + s0; m0 = mn0;
            l1 = l1 * al1 + s1; m1 = mn1;
#pragma unroll
            for (int nb = 0; nb < 8; nb++) {
                acc[nb][0] *= al0; acc[nb][1] *= al0;
                acc[nb][2] *= al1; acc[nb][3] *= al1;
            }

#pragma unroll
            for (int c = 0; c < 4; c++) {
                uint32_t ah[4], al_[4];
                split2(sc[2 * c][0],     sc[2 * c][1],     ah[0], al_[0]);
                split2(sc[2 * c][2],     sc[2 * c][3],     ah[1], al_[1]);
                split2(sc[2 * c + 1][0], sc[2 * c + 1][1], ah[2], al_[2]);
                split2(sc[2 * c + 1][2], sc[2 * c + 1][3], ah[3], al_[3]);
#pragma unroll
                for (int nb = 0; nb < 8; nb++) {
                    int drow = (nb * 8 + gid) * 36 + c * 8 + tig;
                    uint32_t bh[2] = {VHi[drow], VHi[drow + 4]};
                    uint32_t bl[2] = {VLo[drow], VLo[drow + 4]};
                    mma_bf16(acc[nb], ah, bl);
                    mma_bf16(acc[nb], al_, bh);
                    mma_bf16(acc[nb], ah, bh);
                }
            }
        }
        __syncthreads();
    }

    float inv0 = 1.f / l0, inv1 = 1.f / l1;
    int row0 = rmin + gid;
#pragma unroll
    for (int nb = 0; nb < 8; nb++) {
        int col = h * HD + nb * 8 + tig * 2;
        store_frag(oimg, HDIM / 32, row0, col, acc[nb][0] * inv0, acc[nb][1] * inv0);
        store_frag(oimg, HDIM / 32, row0 + 8, col, acc[nb][2] * inv1, acc[nb][3] * inv1);
    }
}

// ---------------- silu(g) * u -> fragment image ----------------
__global__ void silu_mul_frag_kernel(const float* __restrict__ gu,
                                     uint32_t* __restrict__ img) {
    int p = blockIdx.x * 256 + threadIdx.x;   // pair index, SEQ*IDIM/2 total
    int s = p >> 11, c = (p & 2047) << 1;
    const float* row = gu + (size_t)s * GUN;
    float2 g = *(const float2*)(row + c);
    float2 u = *(const float2*)(row + IDIM + c);
    float a = g.x / (1.f + __expf(-g.x)) * u.x;
    float b = g.y / (1.f + __expf(-g.y)) * u.y;
    store_frag(img, IDIM / 32, s, c, a, b);
}

// ---------------- host launch ----------------
extern "C" void kernel_launch(void* const* d_in, const int* in_sizes, int n_in,
                              void* d_out, int out_size) {
    (void)in_sizes; (void)n_in; (void)out_size;

    static bool init = false;
    static float *p_h, *p_qkv, *p_gu;
    static uint32_t *p_wqkv, *p_wo, *p_wgu, *p_wdown, *p_wlm;
    static uint32_t *p_ks, *p_vthi, *p_vtlo, *p_aimg;
    if (!init) {
        cudaGetSymbolAddress((void**)&p_h, g_h);
        cudaGetSymbolAddress((void**)&p_qkv, g_qkv);
        cudaGetSymbolAddress((void**)&p_gu, g_gu);
        cudaGetSymbolAddress((void**)&p_wqkv, wp_qkv);
        cudaGetSymbolAddress((void**)&p_wo, wp_o);
        cudaGetSymbolAddress((void**)&p_wgu, wp_gu);
        cudaGetSymbolAddress((void**)&p_wdown, wp_down);
        cudaGetSymbolAddress((void**)&p_wlm, wp_lm);
        cudaGetSymbolAddress((void**)&p_ks, g_ks);
        cudaGetSymbolAddress((void**)&p_vthi, g_vthi);
        cudaGetSymbolAddress((void**)&p_vtlo, g_vtlo);
        cudaGetSymbolAddress((void**)&p_aimg, g_aimg);
        init = true;
    }

    const int*   ids    = (const int*)d_in[0];
    const int*   pos    = (const int*)d_in[1];
    const float* audio  = (const float*)d_in[2];
    const int*   aoff   = (const int*)d_in[3];
    const float* embw   = (const float*)d_in[4];
    const float* q_w    = (const float*)d_in[5];
    const float* k_w    = (const float*)d_in[6];
    const float* v_w    = (const float*)d_in[7];
    const float* o_w    = (const float*)d_in[8];
    const float* qn_w   = (const float*)d_in[9];
    const float* kn_w   = (const float*)d_in[10];
    const float* ln1_w  = (const float*)d_in[11];
    const float* ln2_w  = (const float*)d_in[12];
    const float* gate_w = (const float*)d_in[13];
    const float* up_w   = (const float*)d_in[14];
    const float* down_w = (const float*)d_in[15];
    const float* norm_w = (const float*)d_in[16];
    const float* lm_w   = (const float*)d_in[17];

    float* out    = (float*)d_out;
    float* logits = out;
    float* pk     = out + (size_t)SEQ * VOCAB;
    float* pv     = pk + (size_t)NLAYER * NKV * SEQ * HD;

    const int BIG = 1 << 30;

#define PREP_LAYER(l)                                                               \
    {                                                                               \
        prep_w_kernel<<<dim3(QKVN / 128, HDIM / 32), 256>>>(                        \
            q_w + (size_t)(l) * HDIM * (NH * HD), NH * HD,                          \
            k_w + (size_t)(l) * HDIM * (NKV * HD), NKV * HD,                        \
            v_w + (size_t)(l) * HDIM * (NKV * HD), NKV * HD,                        \
            NH * HD, NH * HD + NKV * HD,                                            \
            p_wqkv + (size_t)(l) * HDIM * QKVN);                                    \
        prep_w_kernel<<<dim3(HDIM / 128, HDIM / 32), 256>>>(                        \
            o_w + (size_t)(l) * HDIM * HDIM, HDIM, o_w, HDIM, o_w, HDIM, BIG, BIG,  \
            p_wo + (size_t)(l) * HDIM * HDIM);                                      \
        prep_w_kernel<<<dim3(GUN / 128, HDIM / 32), 256>>>(                         \
            gate_w + (size_t)(l) * HDIM * IDIM, IDIM,                               \
            up_w + (size_t)(l) * HDIM * IDIM, IDIM,                                 \
            up_w, IDIM, IDIM, BIG,                                                  \
            p_wgu + (size_t)(l) * HDIM * GUN);                                      \
        prep_w_kernel<<<dim3(HDIM / 128, IDIM / 32), 256>>>(                        \
            down_w + (size_t)(l) * IDIM * HDIM, HDIM, down_w, HDIM, down_w, HDIM,   \
            BIG, BIG, p_wdown + (size_t)(l) * IDIM * HDIM);                         \
    }

    // Launch order chosen so launch index 5 (ncu -s 5 -c 1) is the layer-0 QKV GEMM.
    embed_scatter_kernel<<<SEQ, 256>>>(ids, embw, audio, aoff, p_h);              // 0
    prep_w_kernel<<<dim3(QKVN / 128, HDIM / 32), 256>>>(                          // 1
        q_w, NH * HD, k_w, NKV * HD, v_w, NKV * HD,
        NH * HD, NH * HD + NKV * HD, p_wqkv);
    prep_w_kernel<<<dim3(HDIM / 128, HDIM / 32), 256>>>(                          // 2
        o_w, HDIM, o_w, HDIM, o_w, HDIM, BIG, BIG, p_wo);
    prep_w_kernel<<<dim3(GUN / 128, HDIM / 32), 256>>>(                           // 3
        gate_w, IDIM, up_w, IDIM, up_w, IDIM, IDIM, BIG, p_wgu);
    rmsnorm_frag_kernel<<<SEQ, 256>>>(p_h, ln1_w, p_aimg);                        // 4
    gemm_bf16x2_kernel<<<dim3(QKVN / 128, SEQ / 128), 256>>>(                     // 5 <- profiled
        p_aimg, p_wqkv, nullptr, p_qkv, SEQ, QKVN, HDIM);
    prep_w_kernel<<<dim3(HDIM / 128, IDIM / 32), 256>>>(                          // 6
        down_w, HDIM, down_w, HDIM, down_w, HDIM, BIG, BIG, p_wdown);
    for (int l = 1; l < NLAYER; l++) PREP_LAYER(l);
    prep_w_kernel<<<dim3(VOCAB / 128, HDIM / 32), 256>>>(
        lm_w, VOCAB, lm_w, VOCAB, lm_w, VOCAB, BIG, BIG, p_wlm);

    for (int l = 0; l < NLAYER; l++) {
        float* pk_l = pk + (size_t)l * NKV * SEQ * HD;
        float* pv_l = pv + (size_t)l * NKV * SEQ * HD;

        if (l > 0) {
            rmsnorm_frag_kernel<<<SEQ, 256>>>(p_h, ln1_w + (size_t)l * HDIM, p_aimg);
            gemm_bf16x2_kernel<<<dim3(QKVN / 128, SEQ / 128), 256>>>(
                p_aimg, p_wqkv + (size_t)l * HDIM * QKVN, nullptr, p_qkv, SEQ, QKVN, HDIM);
        }

        rope_fused_kernel<<<dim3(SEQ, 5), 128>>>(p_qkv, qn_w + (size_t)l * HD,
                                                 kn_w + (size_t)l * HD, pos,
                                                 pk_l, pv_l, p_ks, p_vthi, p_vtlo);

        attn_mma_kernel<<<dim3(SEQ / 128, NH), 256>>>(p_qkv, p_ks, p_vthi, p_vtlo, p_aimg);

        gemm_bf16x2_kernel<<<dim3(HDIM / 128, SEQ / 128), 256>>>(
            p_aimg, p_wo + (size_t)l * HDIM * HDIM, p_h, p_h, SEQ, HDIM, HDIM);

        rmsnorm_frag_kernel<<<SEQ, 256>>>(p_h, ln2_w + (size_t)l * HDIM, p_aimg);
        gemm_bf16x2_kernel<<<dim3(GUN / 128, SEQ / 128), 256>>>(
            p_aimg, p_wgu + (size_t)l * HDIM * GUN, nullptr, p_gu, SEQ, GUN, HDIM);

        silu_mul_frag_kernel<<<(SEQ * IDIM / 2) / 256, 256>>>(p_gu, p_aimg);
        gemm_bf16x2_kernel<<<dim3(HDIM / 128, SEQ / 128), 256>>>(
            p_aimg, p_wdown + (size_t)l * IDIM * HDIM, p_h, p_h, SEQ, HDIM, IDIM);
    }

    rmsnorm_frag_kernel<<<SEQ, 256>>>(p_h, norm_w, p_aimg);
    gemm_bf16x2_kernel<<<dim3(VOCAB / 128, SEQ / 128), 256>>>(
        p_aimg, p_wlm, nullptr, logits, SEQ, VOCAB, HDIM);
#undef PREP_LAYER
}

// round 17
// speedup vs baseline: 1.9975x; 1.0263x over previous
#include <cuda_runtime.h>
#include <cuda_bf16.h>
#include <stdint.h>
#include <math.h>

#define SEQ 2048
#define HDIM 1024
#define NLAYER 4
#define NH 16
#define NKV 4
#define HD 64
#define IDIM 4096
#define VOCAB 32000
#define QKVN 1536
#define GUN 8192

// ---------------- scratch ----------------
__device__ float g_h[SEQ * HDIM];
__device__ float g_qkv[SEQ * QKVN];
__device__ float g_gu[SEQ * GUN];

__device__ uint32_t g_aimg[SEQ * IDIM];

__device__ uint32_t wp_qkv[NLAYER * HDIM * QKVN];
__device__ uint32_t wp_o[NLAYER * HDIM * HDIM];
__device__ uint32_t wp_gu[NLAYER * HDIM * GUN];
__device__ uint32_t wp_down[NLAYER * IDIM * HDIM];
__device__ uint32_t wp_lm[HDIM * VOCAB];

__device__ uint32_t g_ks[NKV * SEQ * 64];
__device__ uint32_t g_vthi[NKV * 64 * (SEQ / 2)];
__device__ uint32_t g_vtlo[NKV * 64 * (SEQ / 2)];

// ---------------- helpers ----------------
__device__ __forceinline__ void split2(float x, float y, uint32_t& hi, uint32_t& lo) {
    __nv_bfloat162 h = __floats2bfloat162_rn(x, y);
    hi = *(uint32_t*)&h;
    __nv_bfloat162 l = __floats2bfloat162_rn(x - __bfloat162float(h.x),
                                             y - __bfloat162float(h.y));
    lo = *(uint32_t*)&l;
}

__device__ __forceinline__ void split1(float x, __nv_bfloat16& hi, __nv_bfloat16& lo) {
    hi = __float2bfloat16_rn(x);
    lo = __float2bfloat16_rn(x - __bfloat162float(hi));
}

__device__ __forceinline__ void store_frag(uint32_t* __restrict__ img, int KT,
                                           int row, int k, float x, float y) {
    int mt = row >> 7, rl = row & 127;
    int kc = k >> 5, kl = k & 31;
    int lane = ((rl & 7) << 2) | ((kl >> 1) & 3);
    int reg = (((kl >> 3) & 1) << 1) | ((rl >> 3) & 1);
    int v = ((kl >> 4) << 3) | (rl >> 4);
    size_t base = ((size_t)mt * KT + kc) * 4096 + v * 256 + lane * 4 + reg;
    uint32_t hi, lo;
    split2(x, y, hi, lo);
    img[base] = hi;
    img[base + 128] = lo;
}

__device__ __forceinline__ void mma_bf16(float* c, const uint32_t* a, const uint32_t* b) {
    asm volatile(
        "mma.sync.aligned.m16n8k16.row.col.f32.bf16.bf16.f32 "
        "{%0,%1,%2,%3}, {%4,%5,%6,%7}, {%8,%9}, {%0,%1,%2,%3};"
        : "+f"(c[0]), "+f"(c[1]), "+f"(c[2]), "+f"(c[3])
        : "r"(a[0]), "r"(a[1]), "r"(a[2]), "r"(a[3]), "r"(b[0]), "r"(b[1]));
}

__device__ __forceinline__ void cp_async16(void* smem, const void* gmem) {
    uint32_t s = (uint32_t)__cvta_generic_to_shared(smem);
    asm volatile("cp.async.cg.shared.global [%0], [%1], 16;" :: "r"(s), "l"(gmem));
}
#define CP_COMMIT() asm volatile("cp.async.commit_group;")
#define CP_WAIT0()  asm volatile("cp.async.wait_group 0;")
#define CP_WAIT1()  asm volatile("cp.async.wait_group 1;")

// ---------------- weight prep ----------------
__global__ void prep_w_kernel(const float* __restrict__ s0, int st0,
                              const float* __restrict__ s1, int st1,
                              const float* __restrict__ s2, int st2,
                              int n1, int n2, uint32_t* __restrict__ out) {
    int kt = blockIdx.y, nt = blockIdx.x, NT = gridDim.x;
    int t = threadIdx.x;
#pragma unroll
    for (int it = 0; it < 4; it++) {
        int slot = it * 256 + t;
        int lane = slot & 31, in = (slot >> 5) & 15, ik = slot >> 9;
        int g = lane >> 2, c = lane & 3;
        int n = nt * 128 + in * 8 + g;
        int kb = kt * 32 + ik * 16 + 2 * c;
        const float* src; int nn; int st;
        if (n >= n2)      { src = s2; nn = n - n2; st = st2; }
        else if (n >= n1) { src = s1; nn = n - n1; st = st1; }
        else              { src = s0; nn = n;      st = st0; }
        float x0 = src[(size_t)(kb + 0) * st + nn];
        float x1 = src[(size_t)(kb + 1) * st + nn];
        float x8 = src[(size_t)(kb + 8) * st + nn];
        float x9 = src[(size_t)(kb + 9) * st + nn];
        uint4 o;
        uint32_t l01, l89;
        split2(x0, x1, o.x, l01);
        split2(x8, x9, o.y, l89);
        o.z = l01; o.w = l89;
        *(uint4*)&out[((size_t)((size_t)kt * NT + nt) * 1024 + slot) * 4] = o;
    }
}

// ---------------- bf16x2 (3-term) tensor-core GEMM ----------------
__global__ __launch_bounds__(256) void gemm_bf16x2_kernel(
    const uint32_t* __restrict__ Aimg, const uint32_t* __restrict__ Bp,
    const float* __restrict__ Res, float* __restrict__ C,
    int M, int N, int K) {
    __shared__ uint32_t Asm[2][4096];
    __shared__ uint32_t Bsm[2][4096];

    int tid = threadIdx.x, lane = tid & 31, warp = tid >> 5;
    int wm = warp >> 2, wn = warp & 3;
    int bnx = blockIdx.x, mt = blockIdx.y;
    int NT = N >> 7, KT = K >> 5;

    float acc[4][4][4];
#pragma unroll
    for (int im = 0; im < 4; im++)
#pragma unroll
        for (int in = 0; in < 4; in++)
#pragma unroll
            for (int r = 0; r < 4; r++) acc[im][in][r] = 0.f;

#define CPAB(kt, st)                                                                 \
    {                                                                                \
        const uint32_t* aS = Aimg + ((size_t)mt * KT + (kt)) * 4096;                 \
        const uint32_t* bS = Bp + ((size_t)(kt) * NT + bnx) * 4096;                  \
        _Pragma("unroll")                                                            \
        for (int i = 0; i < 4; i++) {                                                \
            int s4 = tid + i * 256;                                                  \
            cp_async16(&Asm[st][s4 * 4], aS + s4 * 4);                               \
            cp_async16(&Bsm[st][s4 * 4], bS + s4 * 4);                               \
        }                                                                            \
    }

#define COMPUTE(st)                                                                  \
    {                                                                                \
        _Pragma("unroll")                                                            \
        for (int ik = 0; ik < 2; ik++) {                                             \
            uint32_t ah[4][4], al[4][4], bh[4][2], bl[4][2];                         \
            _Pragma("unroll")                                                        \
            for (int im = 0; im < 4; im++) {                                         \
                *(uint4*)ah[im] = *(const uint4*)&Asm[st][(((ik * 8 + wm * 4 + im) * 2 + 0) * 32 + lane) * 4]; \
                *(uint4*)al[im] = *(const uint4*)&Asm[st][(((ik * 8 + wm * 4 + im) * 2 + 1) * 32 + lane) * 4]; \
            }                                                                        \
            _Pragma("unroll")                                                        \
            for (int in = 0; in < 4; in++) {                                         \
                uint4 qv = *(const uint4*)&Bsm[st][((ik * 16 + wn * 4 + in) * 32 + lane) * 4]; \
                bh[in][0] = qv.x; bh[in][1] = qv.y;                                  \
                bl[in][0] = qv.z; bl[in][1] = qv.w;                                  \
            }                                                                        \
            _Pragma("unroll")                                                        \
            for (int im = 0; im < 4; im++)                                           \
                _Pragma("unroll")                                                    \
                for (int in = 0; in < 4; in++) {                                     \
                    mma_bf16(acc[im][in], ah[im], bl[in]);                           \
                    mma_bf16(acc[im][in], al[im], bh[in]);                           \
                    mma_bf16(acc[im][in], ah[im], bh[in]);                           \
                }                                                                    \
        }                                                                            \
    }

    CPAB(0, 0); CP_COMMIT();
    CP_WAIT0();
    __syncthreads();

    for (int kt = 0; kt < KT; kt++) {
        int st = kt & 1;
        if (kt + 1 < KT) { CPAB(kt + 1, st ^ 1); CP_COMMIT(); }
        COMPUTE(st);
        if (kt + 1 < KT) { CP_WAIT0(); }
        __syncthreads();
    }

    int gid = lane >> 2, tig = lane & 3;
#pragma unroll
    for (int im = 0; im < 4; im++) {
#pragma unroll
        for (int in = 0; in < 4; in++) {
            int row0 = mt * 128 + wm * 64 + im * 16 + gid;
            int col = bnx * 128 + wn * 32 + in * 8 + tig * 2;
            float2 v0 = make_float2(acc[im][in][0], acc[im][in][1]);
            float2 v1 = make_float2(acc[im][in][2], acc[im][in][3]);
            if (Res) {
                float2 r0 = *(const float2*)(Res + (size_t)row0 * N + col);
                float2 r1 = *(const float2*)(Res + (size_t)(row0 + 8) * N + col);
                v0.x += r0.x; v0.y += r0.y;
                v1.x += r1.x; v1.y += r1.y;
            }
            *(float2*)(C + (size_t)row0 * N + col) = v0;
            *(float2*)(C + (size_t)(row0 + 8) * N + col) = v1;
        }
    }
#undef CPAB
#undef COMPUTE
}

// ---------------- embedding + audio scatter ----------------
__global__ void embed_scatter_kernel(const int* __restrict__ ids,
                                     const float* __restrict__ emb,
                                     const float* __restrict__ audio,
                                     const int* __restrict__ aoff,
                                     float* __restrict__ h) {
    int s = blockIdx.x;
    int off = aoff[0];
    const float* src;
    if (s >= off && s < off + 256) src = audio + (size_t)(s - off) * HDIM;
    else                           src = emb + (size_t)ids[s] * HDIM;
    float* dst = h + (size_t)s * HDIM;
    int i = threadIdx.x * 4;
    *(float4*)&dst[i] = *(const float4*)&src[i];
}

// ---------------- RMSNorm -> fragment image ----------------
__global__ void rmsnorm_frag_kernel(const float* __restrict__ x,
                                    const float* __restrict__ w,
                                    uint32_t* __restrict__ img) {
    int s = blockIdx.x;
    const float* xr = x + (size_t)s * HDIM;
    float ss = 0.f;
#pragma unroll
    for (int i = 0; i < 4; i++) { float v = xr[threadIdx.x + i * 256]; ss += v * v; }
    __shared__ float red[8];
#pragma unroll
    for (int o = 16; o; o >>= 1) ss += __shfl_xor_sync(0xffffffffu, ss, o);
    if ((threadIdx.x & 31) == 0) red[threadIdx.x >> 5] = ss;
    __syncthreads();
    if (threadIdx.x < 32) {
        float v = (threadIdx.x < 8) ? red[threadIdx.x] : 0.f;
#pragma unroll
        for (int o = 4; o; o >>= 1) v += __shfl_xor_sync(0xffffffffu, v, o);
        if (threadIdx.x == 0) red[0] = v;
    }
    __syncthreads();
    float r = rsqrtf(red[0] * (1.f / HDIM) + 1e-6f);
#pragma unroll
    for (int i = 0; i < 2; i++) {
        int k = 2 * threadIdx.x + i * 512;
        float a = xr[k] * r * w[k];
        float b = xr[k + 1] * r * w[k + 1];
        store_frag(img, HDIM / 32, s, k, a, b);
    }
}

// ---------------- fused QKV post-process ----------------
__global__ void rope_fused_kernel(float* __restrict__ qkv,
                                  const float* __restrict__ qn_w,
                                  const float* __restrict__ kn_w,
                                  const int* __restrict__ pos_ids,
                                  float* __restrict__ pk_l,
                                  float* __restrict__ pv_l,
                                  uint32_t* __restrict__ ks,
                                  uint32_t* __restrict__ vthi,
                                  uint32_t* __restrict__ vtlo) {
    int s = blockIdx.x;
    int warp = threadIdx.x >> 5, lane = threadIdx.x & 31;
    float pos = (float)pos_ids[s];
    float invf = expf(-((float)lane * (1.f / 32.f)) * 9.210340371976184f);
    float ang = pos * invf;
    float c, sn;
    sincosf(ang, &sn, &c);

    if (blockIdx.y < 4) {
        int h = blockIdx.y * 4 + warp;
        float* x = qkv + (size_t)s * QKVN + h * HD;
        float x0 = x[lane], x1 = x[lane + 32];
        float ss = x0 * x0 + x1 * x1;
#pragma unroll
        for (int o = 16; o; o >>= 1) ss += __shfl_xor_sync(0xffffffffu, ss, o);
        float r = rsqrtf(ss * (1.f / HD) + 1e-6f);
        x0 = x0 * r * qn_w[lane];
        x1 = x1 * r * qn_w[lane + 32];
        float o0 = x0 * c - x1 * sn;
        float o1 = x1 * c + x0 * sn;
        x[lane] = o0; x[lane + 32] = o1;
    } else {
        int kvh = warp;
        const float* x = qkv + (size_t)s * QKVN + NH * HD + kvh * HD;
        float x0 = x[lane], x1 = x[lane + 32];
        float ss = x0 * x0 + x1 * x1;
#pragma unroll
        for (int o = 16; o; o >>= 1) ss += __shfl_xor_sync(0xffffffffu, ss, o);
        float r = rsqrtf(ss * (1.f / HD) + 1e-6f);
        x0 = x0 * r * kn_w[lane];
        x1 = x1 * r * kn_w[lane + 32];
        float o0 = x0 * c - x1 * sn;
        float o1 = x1 * c + x0 * sn;
        size_t row = (size_t)kvh * SEQ + s;
        float* pp = pk_l + row * HD;
        pp[lane] = o0; pp[lane + 32] = o1;
        __nv_bfloat16* k16 = (__nv_bfloat16*)(ks + row * 64);
        __nv_bfloat16 h0, l0, h1, l1;
        split1(o0, h0, l0);
        split1(o1, h1, l1);
        k16[lane] = h0;       k16[lane + 32] = h1;
        k16[64 + lane] = l0;  k16[64 + lane + 32] = l1;

        int sp = s >> 1, sb = s & 1;
#pragma unroll
        for (int i = 0; i < 2; i++) {
            int e = threadIdx.x + i * 128;
            int kv = e >> 6, d = e & 63;
            float v = qkv[(size_t)s * QKVN + (NH + NKV) * HD + e];
            pv_l[((size_t)kv * SEQ + s) * HD + d] = v;
            __nv_bfloat16 vh, vl;
            split1(v, vh, vl);
            size_t w16 = (((size_t)kv * 64 + d) * (SEQ / 2) + sp);
            ((__nv_bfloat16*)vthi)[w16 * 2 + sb] = vh;
            ((__nv_bfloat16*)vtlo)[w16 * 2 + sb] = vl;
        }
    }
}

// ---------------- tensor-core flash attention (double-buffered) -> fragment image ----------------
// dynamic smem: 2 stages x (KHi,KLo,VHi,VLo each 64*36 uint32) = 73728 B
#define ATTN_STAGE 9216
#define ATTN_SMEM (2 * ATTN_STAGE * 4)
__global__ __launch_bounds__(256) void attn_mma_kernel(const float* __restrict__ q,
                                                       const uint32_t* __restrict__ Ks,
                                                       const uint32_t* __restrict__ Vthi,
                                                       const uint32_t* __restrict__ Vtlo,
                                                       uint32_t* __restrict__ oimg) {
    extern __shared__ uint32_t smd[];

    int qb = blockIdx.x, h = blockIdx.y, kvh = h >> 2;
    int tid = threadIdx.x, w = tid >> 5, lane = tid & 31;
    int gid = lane >> 2, tig = lane & 3;

    uint32_t qh[4][4], ql[4][4];
    int rmin = qb * 128 + w * 16;
    {
        const float* q0 = q + (size_t)(rmin + gid) * QKVN + h * HD;
        const float* q1 = q0 + 8 * QKVN;
#pragma unroll
        for (int c = 0; c < 4; c++) {
            float2 x0 = *(const float2*)(q0 + c * 16 + tig * 2);
            float2 x1 = *(const float2*)(q1 + c * 16 + tig * 2);
            float2 x2 = *(const float2*)(q0 + c * 16 + 8 + tig * 2);
            float2 x3 = *(const float2*)(q1 + c * 16 + 8 + tig * 2);
            split2(x0.x * 0.125f, x0.y * 0.125f, qh[c][0], ql[c][0]);
            split2(x1.x * 0.125f, x1.y * 0.125f, qh[c][1], ql[c][1]);
            split2(x2.x * 0.125f, x2.y * 0.125f, qh[c][2], ql[c][2]);
            split2(x3.x * 0.125f, x3.y * 0.125f, qh[c][3], ql[c][3]);
        }
    }

    float m0 = -1e30f, m1 = -1e30f, l0 = 0.f, l1 = 0.f;
    float acc[8][4];
#pragma unroll
    for (int nb = 0; nb < 8; nb++)
#pragma unroll
        for (int r = 0; r < 4; r++) acc[nb][r] = 0.f;

    int ktend = 2 * qb + 1;

#define LOADTILE(kt, st)                                                             \
    {                                                                                \
        uint32_t* KH = smd + (st) * ATTN_STAGE;                                      \
        uint32_t* KL = KH + 2304;                                                    \
        uint32_t* VH = KL + 2304;                                                    \
        uint32_t* VL = VH + 2304;                                                    \
        _Pragma("unroll")                                                            \
        for (int i = 0; i < 4; i++) {                                                \
            int c0 = tid + i * 256;                                                  \
            int row = c0 >> 4, part = c0 & 15;                                       \
            const uint32_t* src = Ks + ((size_t)(kvh * SEQ + (kt) * 64 + row)) * 64  \
                                  + ((part >> 3) * 32) + ((part & 7) * 4);           \
            uint32_t* dst = ((part >> 3) ? KL : KH) + row * 36 + (part & 7) * 4;     \
            cp_async16(dst, src);                                                    \
        }                                                                            \
        _Pragma("unroll")                                                            \
        for (int i = 0; i < 4; i++) {                                                \
            int c0 = tid + i * 256;                                                  \
            int d = c0 >> 4, part = c0 & 15;                                         \
            const uint32_t* src = ((part >> 3) ? Vtlo : Vthi)                        \
                                  + ((size_t)kvh * 64 + d) * (SEQ / 2) + (kt) * 32   \
                                  + (part & 7) * 4;                                  \
            uint32_t* dst = ((part >> 3) ? VL : VH) + d * 36 + (part & 7) * 4;       \
            cp_async16(dst, src);                                                    \
        }                                                                            \
        CP_COMMIT();                                                                 \
    }

    LOADTILE(0, 0);

    for (int kt = 0; kt <= ktend; kt++) {
        int st = kt & 1;
        if (kt < ktend) LOADTILE(kt + 1, st ^ 1);
        if (kt < ktend) { CP_WAIT1(); } else { CP_WAIT0(); }
        __syncthreads();

        uint32_t* KH = smd + st * ATTN_STAGE;
        uint32_t* KL = KH + 2304;
        uint32_t* VH = KL + 2304;
        uint32_t* VL = VH + 2304;

        bool skip = (kt * 64 > rmin + 15);
        if (!skip) {
            float sc[8][4];
#pragma unroll
            for (int nb = 0; nb < 8; nb++)
#pragma unroll
                for (int r = 0; r < 4; r++) sc[nb][r] = 0.f;

#pragma unroll
            for (int c = 0; c < 4; c++) {
#pragma unroll
                for (int nb = 0; nb < 8; nb++) {
                    int srow = (nb * 8 + gid) * 36 + c * 8 + tig;
                    uint32_t bh[2] = {KH[srow], KH[srow + 4]};
                    uint32_t bl[2] = {KL[srow], KL[srow + 4]};
                    mma_bf16(sc[nb], qh[c], bl);
                    mma_bf16(sc[nb], ql[c], bh);
                    mma_bf16(sc[nb], qh[c], bh);
                }
            }

            if (kt * 64 + 63 > rmin) {
                int r0 = rmin + gid, r1 = rmin + 8 + gid;
#pragma unroll
                for (int nb = 0; nb < 8; nb++) {
#pragma unroll
                    for (int j = 0; j < 2; j++) {
                        int col = kt * 64 + nb * 8 + tig * 2 + j;
                        if (col > r0) sc[nb][j] = -1e30f;
                        if (col > r1) sc[nb][2 + j] = -1e30f;
                    }
                }
            }

            float mx0 = -1e30f, mx1 = -1e30f;
#pragma unroll
            for (int nb = 0; nb < 8; nb++) {
                mx0 = fmaxf(mx0, fmaxf(sc[nb][0], sc[nb][1]));
                mx1 = fmaxf(mx1, fmaxf(sc[nb][2], sc[nb][3]));
            }
            mx0 = fmaxf(mx0, __shfl_xor_sync(0xffffffffu, mx0, 1));
            mx0 = fmaxf(mx0, __shfl_xor_sync(0xffffffffu, mx0, 2));
            mx1 = fmaxf(mx1, __shfl_xor_sync(0xffffffffu, mx1, 1));
            mx1 = fmaxf(mx1, __shfl_xor_sync(0xffffffffu, mx1, 2));
            float mn0 = fmaxf(m0, mx0), mn1 = fmaxf(m1, mx1);
            float al0 = __expf(m0 - mn0), al1 = __expf(m1 - mn1);
            float s0 = 0.f, s1 = 0.f;
#pragma unroll
            for (int nb = 0; nb < 8; nb++) {
                sc[nb][0] = __expf(sc[nb][0] - mn0);
                sc[nb][1] = __expf(sc[nb][1] - mn0);
                sc[nb][2] = __expf(sc[nb][2] - mn1);
                sc[nb][3] = __expf(sc[nb][3] - mn1);
                s0 += sc[nb][0] + sc[nb][1];
                s1 += sc[nb][2] + sc[nb][3];
            }
            s0 += __shfl_xor_sync(0xffffffffu, s0, 1);
            s0 += __shfl_xor_sync(0xffffffffu, s0, 2);
            s1 += __shfl_xor_sync(0xffffffffu, s1, 1);
            s1 += __shfl_xor_sync(0xffffffffu, s1, 2);
            l0 = l0 * al0 + s0; m0 = mn0;
            l1 = l1 * al1 + s1; m1 = mn1;
#pragma unroll
            for (int nb = 0; nb < 8; nb++) {
                acc[nb][0] *= al0; acc[nb][1] *= al0;
                acc[nb][2] *= al1; acc[nb][3] *= al1;
            }

#pragma unroll
            for (int c = 0; c < 4; c++) {
                uint32_t ah[4], al_[4];
                split2(sc[2 * c][0],     sc[2 * c][1],     ah[0], al_[0]);
                split2(sc[2 * c][2],     sc[2 * c][3],     ah[1], al_[1]);
                split2(sc[2 * c + 1][0], sc[2 * c + 1][1], ah[2], al_[2]);
                split2(sc[2 * c + 1][2], sc[2 * c + 1][3], ah[3], al_[3]);
#pragma unroll
                for (int nb = 0; nb < 8; nb++) {
                    int drow = (nb * 8 + gid) * 36 + c * 8 + tig;
                    uint32_t bh[2] = {VH[drow], VH[drow + 4]};
                    uint32_t bl[2] = {VL[drow], VL[drow + 4]};
                    mma_bf16(acc[nb], ah, bl);
                    mma_bf16(acc[nb], al_, bh);
                    mma_bf16(acc[nb], ah, bh);
                }
            }
        }
        __syncthreads();
    }
#undef LOADTILE

    float inv0 = 1.f / l0, inv1 = 1.f / l1;
    int row0 = rmin + gid;
#pragma unroll
    for (int nb = 0; nb < 8; nb++) {
        int col = h * HD + nb * 8 + tig * 2;
        store_frag(oimg, HDIM / 32, row0, col, acc[nb][0] * inv0, acc[nb][1] * inv0);
        store_frag(oimg, HDIM / 32, row0 + 8, col, acc[nb][2] * inv1, acc[nb][3] * inv1);
    }
}

// ---------------- silu(g) * u -> fragment image ----------------
__global__ void silu_mul_frag_kernel(const float* __restrict__ gu,
                                     uint32_t* __restrict__ img) {
    int p = blockIdx.x * 256 + threadIdx.x;
    int s = p >> 11, c = (p & 2047) << 1;
    const float* row = gu + (size_t)s * GUN;
    float2 g = *(const float2*)(row + c);
    float2 u = *(const float2*)(row + IDIM + c);
    float a = g.x / (1.f + __expf(-g.x)) * u.x;
    float b = g.y / (1.f + __expf(-g.y)) * u.y;
    store_frag(img, IDIM / 32, s, c, a, b);
}

// ---------------- host launch ----------------
extern "C" void kernel_launch(void* const* d_in, const int* in_sizes, int n_in,
                              void* d_out, int out_size) {
    (void)in_sizes; (void)n_in; (void)out_size;

    static bool init = false;
    static float *p_h, *p_qkv, *p_gu;
    static uint32_t *p_wqkv, *p_wo, *p_wgu, *p_wdown, *p_wlm;
    static uint32_t *p_ks, *p_vthi, *p_vtlo, *p_aimg;
    static cudaStream_t s2;
    static cudaEvent_t evFork, evJoin;
    if (!init) {
        cudaGetSymbolAddress((void**)&p_h, g_h);
        cudaGetSymbolAddress((void**)&p_qkv, g_qkv);
        cudaGetSymbolAddress((void**)&p_gu, g_gu);
        cudaGetSymbolAddress((void**)&p_wqkv, wp_qkv);
        cudaGetSymbolAddress((void**)&p_wo, wp_o);
        cudaGetSymbolAddress((void**)&p_wgu, wp_gu);
        cudaGetSymbolAddress((void**)&p_wdown, wp_down);
        cudaGetSymbolAddress((void**)&p_wlm, wp_lm);
        cudaGetSymbolAddress((void**)&p_ks, g_ks);
        cudaGetSymbolAddress((void**)&p_vthi, g_vthi);
        cudaGetSymbolAddress((void**)&p_vtlo, g_vtlo);
        cudaGetSymbolAddress((void**)&p_aimg, g_aimg);
        cudaStreamCreateWithFlags(&s2, cudaStreamNonBlocking);
        cudaEventCreateWithFlags(&evFork, cudaEventDisableTiming);
        cudaEventCreateWithFlags(&evJoin, cudaEventDisableTiming);
        cudaFuncSetAttribute(attn_mma_kernel,
                             cudaFuncAttributeMaxDynamicSharedMemorySize, ATTN_SMEM);
        init = true;
    }

    const int*   ids    = (const int*)d_in[0];
    const int*   pos    = (const int*)d_in[1];
    const float* audio  = (const float*)d_in[2];
    const int*   aoff   = (const int*)d_in[3];
    const float* embw   = (const float*)d_in[4];
    const float* q_w    = (const float*)d_in[5];
    const float* k_w    = (const float*)d_in[6];
    const float* v_w    = (const float*)d_in[7];
    const float* o_w    = (const float*)d_in[8];
    const float* qn_w   = (const float*)d_in[9];
    const float* kn_w   = (const float*)d_in[10];
    const float* ln1_w  = (const float*)d_in[11];
    const float* ln2_w  = (const float*)d_in[12];
    const float* gate_w = (const float*)d_in[13];
    const float* up_w   = (const float*)d_in[14];
    const float* down_w = (const float*)d_in[15];
    const float* norm_w = (const float*)d_in[16];
    const float* lm_w   = (const float*)d_in[17];

    float* out    = (float*)d_out;
    float* logits = out;
    float* pk     = out + (size_t)SEQ * VOCAB;
    float* pv     = pk + (size_t)NLAYER * NKV * SEQ * HD;

    const int BIG = 1 << 30;

    // ---- main stream: embed + layer-0 QKV weight prep ----
    embed_scatter_kernel<<<SEQ, 256>>>(ids, embw, audio, aoff, p_h);
    prep_w_kernel<<<dim3(QKVN / 128, HDIM / 32), 256>>>(
        q_w, NH * HD, k_w, NKV * HD, v_w, NKV * HD,
        NH * HD, NH * HD + NKV * HD, p_wqkv);

    // ---- fork: remaining weight prep on side stream ----
    cudaEventRecord(evFork, 0);
    cudaStreamWaitEvent(s2, evFork, 0);
    for (int l = 0; l < NLAYER; l++) {
        if (l > 0)
            prep_w_kernel<<<dim3(QKVN / 128, HDIM / 32), 256, 0, s2>>>(
                q_w + (size_t)l * HDIM * (NH * HD), NH * HD,
                k_w + (size_t)l * HDIM * (NKV * HD), NKV * HD,
                v_w + (size_t)l * HDIM * (NKV * HD), NKV * HD,
                NH * HD, NH * HD + NKV * HD,
                p_wqkv + (size_t)l * HDIM * QKVN);
        prep_w_kernel<<<dim3(HDIM / 128, HDIM / 32), 256, 0, s2>>>(
            o_w + (size_t)l * HDIM * HDIM, HDIM, o_w, HDIM, o_w, HDIM, BIG, BIG,
            p_wo + (size_t)l * HDIM * HDIM);
        prep_w_kernel<<<dim3(GUN / 128, HDIM / 32), 256, 0, s2>>>(
            gate_w + (size_t)l * HDIM * IDIM, IDIM,
            up_w + (size_t)l * HDIM * IDIM, IDIM,
            up_w, IDIM, IDIM, BIG,
            p_wgu + (size_t)l * HDIM * GUN);
        prep_w_kernel<<<dim3(HDIM / 128, IDIM / 32), 256, 0, s2>>>(
            down_w + (size_t)l * IDIM * HDIM, HDIM, down_w, HDIM, down_w, HDIM, BIG, BIG,
            p_wdown + (size_t)l * IDIM * HDIM);
    }
    prep_w_kernel<<<dim3(VOCAB / 128, HDIM / 32), 256, 0, s2>>>(
        lm_w, VOCAB, lm_w, VOCAB, lm_w, VOCAB, BIG, BIG, p_wlm);
    cudaEventRecord(evJoin, s2);

    bool joined = false;
    for (int l = 0; l < NLAYER; l++) {
        float* pk_l = pk + (size_t)l * NKV * SEQ * HD;
        float* pv_l = pv + (size_t)l * NKV * SEQ * HD;

        rmsnorm_frag_kernel<<<SEQ, 256>>>(p_h, ln1_w + (size_t)l * HDIM, p_aimg);
        gemm_bf16x2_kernel<<<dim3(QKVN / 128, SEQ / 128), 256>>>(
            p_aimg, p_wqkv + (size_t)l * HDIM * QKVN, nullptr, p_qkv, SEQ, QKVN, HDIM);

        rope_fused_kernel<<<dim3(SEQ, 5), 128>>>(p_qkv, qn_w + (size_t)l * HD,
                                                 kn_w + (size_t)l * HD, pos,
                                                 pk_l, pv_l, p_ks, p_vthi, p_vtlo);

        attn_mma_kernel<<<dim3(SEQ / 128, NH), 256, ATTN_SMEM>>>(
            p_qkv, p_ks, p_vthi, p_vtlo, p_aimg);

        if (!joined) { cudaStreamWaitEvent(0, evJoin, 0); joined = true; }

        gemm_bf16x2_kernel<<<dim3(HDIM / 128, SEQ / 128), 256>>>(
            p_aimg, p_wo + (size_t)l * HDIM * HDIM, p_h, p_h, SEQ, HDIM, HDIM);

        rmsnorm_frag_kernel<<<SEQ, 256>>>(p_h, ln2_w + (size_t)l * HDIM, p_aimg);
        gemm_bf16x2_kernel<<<dim3(GUN / 128, SEQ / 128), 256>>>(
            p_aimg, p_wgu + (size_t)l * HDIM * GUN, nullptr, p_gu, SEQ, GUN, HDIM);

        silu_mul_frag_kernel<<<(SEQ * IDIM / 2) / 256, 256>>>(p_gu, p_aimg);
        gemm_bf16x2_kernel<<<dim3(HDIM / 128, SEQ / 128), 256>>>(
            p_aimg, p_wdown + (size_t)l * IDIM * HDIM, p_h, p_h, SEQ, HDIM, IDIM);
    }

    rmsnorm_frag_kernel<<<SEQ, 256>>>(p_h, norm_w, p_aimg);
    gemm_bf16x2_kernel<<<dim3(VOCAB / 128, SEQ / 128), 256>>>(
        p_aimg, p_wlm, nullptr, logits, SEQ, VOCAB, HDIM);
}